// round 1
// baseline (speedup 1.0000x reference)
#include <cuda_runtime.h>

// ---------------------------------------------------------------------------
// Problem constants
// ---------------------------------------------------------------------------
#define B_   4
#define N_   1024
#define DM_  1024
#define H_   16
#define DK_  64
#define DV_  1024

// ---------------------------------------------------------------------------
// Scratch (device globals; no allocations allowed)
// ---------------------------------------------------------------------------
__device__ float g_Q [B_ * H_ * N_ * DK_];   //  64 MB  [b,h,n,k]
__device__ float g_K [B_ * H_ * N_ * DK_];   //  64 MB  [b,h,n,k]
__device__ float g_Kt[B_ * H_ * DK_ * N_];   //  64 MB  [b,h,k,n]
__device__ float g_V [B_ * H_ * N_ * DV_];   // 256 MB  [b,h,n,v]
__device__ float g_S [B_ * H_ * N_ * N_];    // 256 MB  scores / weights (in place)
__device__ float g_O [B_ * H_ * N_ * DV_];   // 256 MB  attention output

// ---------------------------------------------------------------------------
// Generic batched fp32 SGEMM:  C = alpha * (A @ B)
//   A: M x K row-major (lda), B: K x N row-major (ldb), C: M x N (ldc)
//   Batch index z = blockIdx.z decomposed as zo = z / inner, zi = z % inner.
//   Per-operand offset = zo * s?o + zi * s?i.  Requires M%BM==N%BN==K%BK==0.
// ---------------------------------------------------------------------------
template<int BM, int BN, int BK, int TM, int TN>
__global__ void __launch_bounds__((BM / TM) * (BN / TN))
sgemm_kernel(const float* __restrict__ A, const float* __restrict__ Bm,
             float* __restrict__ C,
             int Mdim, int Ndim, int Kdim,
             int lda, int ldb, int ldc,
             long long sAo, long long sAi,
             long long sBo, long long sBi,
             long long sCo, long long sCi,
             int inner, float alpha)
{
    constexpr int THREADS = (BM / TM) * (BN / TN);

    const int z  = blockIdx.z;
    const int zo = z / inner;
    const int zi = z - zo * inner;
    A  += zo * sAo + zi * sAi;
    Bm += zo * sBo + zi * sBi;
    C  += zo * sCo + zi * sCi;

    __shared__ float As[BK][BM];
    __shared__ float Bs[BK][BN];

    const int tid  = threadIdx.x;
    const int m0   = blockIdx.y * BM;
    const int n0   = blockIdx.x * BN;
    const int tcol = tid % (BN / TN);   // n direction
    const int trow = tid / (BN / TN);   // m direction

    float acc[TM][TN];
#pragma unroll
    for (int i = 0; i < TM; i++)
#pragma unroll
        for (int j = 0; j < TN; j++) acc[i][j] = 0.0f;

    constexpr int A_F4 = BM * BK / (THREADS * 4);
    constexpr int B_F4 = BK * BN / (THREADS * 4);

    for (int kt = 0; kt < Kdim; kt += BK) {
        // --- load A tile (BM x BK), store transposed into As[k][m] ---
#pragma unroll
        for (int i = 0; i < A_F4; i++) {
            int f    = tid + i * THREADS;
            int row  = f / (BK / 4);
            int kcol = (f % (BK / 4)) * 4;
            float4 v = *(const float4*)(A + (long long)(m0 + row) * lda + kt + kcol);
            As[kcol + 0][row] = v.x;
            As[kcol + 1][row] = v.y;
            As[kcol + 2][row] = v.z;
            As[kcol + 3][row] = v.w;
        }
        // --- load B tile (BK x BN) ---
#pragma unroll
        for (int i = 0; i < B_F4; i++) {
            int f    = tid + i * THREADS;
            int krow = f / (BN / 4);
            int ncol = (f % (BN / 4)) * 4;
            *(float4*)(&Bs[krow][ncol]) =
                *(const float4*)(Bm + (long long)(kt + krow) * ldb + n0 + ncol);
        }
        __syncthreads();

#pragma unroll
        for (int kk = 0; kk < BK; kk++) {
            float ra[TM], rb[TN];
#pragma unroll
            for (int i = 0; i < TM / 4; i++)
                *(float4*)&ra[i * 4] = *(const float4*)&As[kk][trow * TM + i * 4];
#pragma unroll
            for (int j = 0; j < TN / 4; j++)
                *(float4*)&rb[j * 4] = *(const float4*)&Bs[kk][tcol * TN + j * 4];
#pragma unroll
            for (int i = 0; i < TM; i++)
#pragma unroll
                for (int j = 0; j < TN; j++)
                    acc[i][j] += ra[i] * rb[j];
        }
        __syncthreads();
    }

    // --- write back ---
#pragma unroll
    for (int i = 0; i < TM; i++) {
        long long crow = (long long)(m0 + trow * TM + i) * ldc + n0 + tcol * TN;
#pragma unroll
        for (int j = 0; j < TN; j += 4) {
            float4 v;
            v.x = acc[i][j + 0] * alpha;
            v.y = acc[i][j + 1] * alpha;
            v.z = acc[i][j + 2] * alpha;
            v.w = acc[i][j + 3] * alpha;
            *(float4*)(C + crow + j) = v;
        }
    }
}

// ---------------------------------------------------------------------------
// Transpose per batch: in [Z, N_, DK_] -> out [Z, DK_, N_]
// ---------------------------------------------------------------------------
__global__ void transpose_k_kernel(const float* __restrict__ in, float* __restrict__ out)
{
    __shared__ float tile[32][33];
    const int z  = blockIdx.z;
    const int n0 = blockIdx.x * 32;
    const int k0 = blockIdx.y * 32;
    const float* ip = in  + (long long)z * N_ * DK_;
    float*       op = out + (long long)z * DK_ * N_;
    const int tx = threadIdx.x, ty = threadIdx.y;   // 32 x 8
#pragma unroll
    for (int i = 0; i < 32; i += 8)
        tile[ty + i][tx] = ip[(long long)(n0 + ty + i) * DK_ + k0 + tx];
    __syncthreads();
#pragma unroll
    for (int i = 0; i < 32; i += 8)
        op[(long long)(k0 + ty + i) * N_ + n0 + tx] = tile[tx][ty + i];
}

// ---------------------------------------------------------------------------
// Row softmax (in place). One block (256 threads) per 1024-wide row.
// ---------------------------------------------------------------------------
__global__ void softmax_kernel(float* __restrict__ S)
{
    __shared__ float red[8];
    float4* p = (float4*)(S + (long long)blockIdx.x * N_);
    const int tid  = threadIdx.x;          // 256 threads, 4 elems each
    const int lane = tid & 31;
    const int warp = tid >> 5;

    float4 x = p[tid];

    // --- max ---
    float m = fmaxf(fmaxf(x.x, x.y), fmaxf(x.z, x.w));
#pragma unroll
    for (int o = 16; o; o >>= 1) m = fmaxf(m, __shfl_xor_sync(0xffffffffu, m, o));
    if (lane == 0) red[warp] = m;
    __syncthreads();
    m = red[0];
#pragma unroll
    for (int j = 1; j < 8; j++) m = fmaxf(m, red[j]);
    __syncthreads();

    // --- exp + sum ---
    x.x = __expf(x.x - m);
    x.y = __expf(x.y - m);
    x.z = __expf(x.z - m);
    x.w = __expf(x.w - m);
    float s = x.x + x.y + x.z + x.w;
#pragma unroll
    for (int o = 16; o; o >>= 1) s += __shfl_xor_sync(0xffffffffu, s, o);
    if (lane == 0) red[warp] = s;
    __syncthreads();
    s = red[0];
#pragma unroll
    for (int j = 1; j < 8; j++) s += red[j];

    const float inv = 1.0f / s;
    x.x *= inv; x.y *= inv; x.z *= inv; x.w *= inv;
    p[tid] = x;
}

// ---------------------------------------------------------------------------
// Launch
// ---------------------------------------------------------------------------
extern "C" void kernel_launch(void* const* d_in, const int* in_sizes, int n_in,
                              void* d_out, int out_size)
{
    (void)in_sizes; (void)n_in; (void)out_size;

    const float* query = (const float*)d_in[0];   // [4,1024,1024]
    const float* key   = (const float*)d_in[1];   // [4,1024,1024]
    const float* value = (const float*)d_in[2];   // [4,1024,1024]
    const float* w_q   = (const float*)d_in[3];   // [16,1024,64]
    const float* w_k   = (const float*)d_in[4];   // [16,1024,64]
    const float* w_v   = (const float*)d_in[5];   // [16,1024,1024]
    const float* w_o   = (const float*)d_in[6];   // [1024,16384]
    float*       out   = (float*)d_out;           // [4,1024,1024]

    float *Q, *K, *Kt, *V, *S, *O;
    cudaGetSymbolAddress((void**)&Q,  g_Q);
    cudaGetSymbolAddress((void**)&K,  g_K);
    cudaGetSymbolAddress((void**)&Kt, g_Kt);
    cudaGetSymbolAddress((void**)&V,  g_V);
    cudaGetSymbolAddress((void**)&S,  g_S);
    cudaGetSymbolAddress((void**)&O,  g_O);

    const long long MB  = 1024LL * 1024LL;   // 1M elements
    const int ZBH = B_ * H_;                 // 64

    // ---- 1. Q projection: per (b,h)  [1024,1024] @ [1024,64] -> [1024,64]
    sgemm_kernel<128, 64, 16, 8, 4><<<dim3(1, 8, ZBH), 256>>>(
        query, w_q, Q, N_, DK_, DM_,
        DM_, DK_, DK_,
        /*sAo*/ (long long)N_ * DM_, 0,
        /*sBo*/ 0, (long long)DM_ * DK_,
        /*sCo*/ (long long)H_ * N_ * DK_, (long long)N_ * DK_,
        /*inner*/ H_, 1.0f);

    // ---- 2. K projection
    sgemm_kernel<128, 64, 16, 8, 4><<<dim3(1, 8, ZBH), 256>>>(
        key, w_k, K, N_, DK_, DM_,
        DM_, DK_, DK_,
        (long long)N_ * DM_, 0,
        0, (long long)DM_ * DK_,
        (long long)H_ * N_ * DK_, (long long)N_ * DK_,
        H_, 1.0f);

    // ---- 2b. transpose K -> Kt  [z,1024,64] -> [z,64,1024]
    transpose_k_kernel<<<dim3(N_ / 32, DK_ / 32, ZBH), dim3(32, 8)>>>(K, Kt);

    // ---- 3. scores = (Q @ K^T) / 8 : per z  [1024,64] @ [64,1024]
    sgemm_kernel<128, 128, 16, 8, 8><<<dim3(8, 8, ZBH), 256>>>(
        Q, Kt, S, N_, N_, DK_,
        DK_, N_, N_,
        (long long)N_ * DK_, 0,
        (long long)DK_ * N_, 0,
        (long long)N_ * N_, 0,
        1, 0.125f);

    // ---- 4. softmax rows (in place)
    softmax_kernel<<<ZBH * N_, 256>>>(S);

    // ---- 5. V projection: per (b,h)  [1024,1024] @ [1024,1024]
    sgemm_kernel<128, 128, 16, 8, 8><<<dim3(8, 8, ZBH), 256>>>(
        value, w_v, V, N_, DV_, DM_,
        DM_, DV_, DV_,
        (long long)N_ * DM_, 0,
        0, (long long)DM_ * DV_,
        (long long)H_ * N_ * DV_, (long long)N_ * DV_,
        H_, 1.0f);

    // ---- 6. attention out = weights @ V : per z  [1024,1024] @ [1024,1024]
    sgemm_kernel<128, 128, 16, 8, 8><<<dim3(8, 8, ZBH), 256>>>(
        S, V, O, N_, DV_, N_,
        N_, DV_, DV_,
        (long long)N_ * N_, 0,
        (long long)N_ * DV_, 0,
        (long long)N_ * DV_, 0,
        1, 1.0f);

    // ---- 7. final: per b  w_o[1024,16384] @ O[b][16384,1024] -> out[b][1024,1024]
    sgemm_kernel<128, 128, 16, 8, 8><<<dim3(8, 8, B_), 256>>>(
        w_o, O, out, DM_, DV_, H_ * N_,
        H_ * N_, DV_, DV_,
        0, 0,
        (long long)H_ * N_ * DV_, 0,
        (long long)DM_ * DV_, 0,
        1, 1.0f);
}

// round 4
// speedup vs baseline: 2.1468x; 2.1468x over previous
#include <cuda_runtime.h>
#include <cuda_bf16.h>
#include <cstdint>

// ---------------------------------------------------------------------------
// Problem constants
// ---------------------------------------------------------------------------
#define B_   4
#define N_   1024
#define DM_  1024
#define H_   16
#define DK_  64
#define DV_  1024

// ---------------------------------------------------------------------------
// Scratch (device globals; no allocations allowed). hi/lo bf16 split pairs.
// ---------------------------------------------------------------------------
__device__ __nv_bfloat16 g_qh [B_ * N_ * DM_],  g_ql [B_ * N_ * DM_];
__device__ __nv_bfloat16 g_kh [B_ * N_ * DM_],  g_kl [B_ * N_ * DM_];
__device__ __nv_bfloat16 g_vh [B_ * N_ * DM_],  g_vl [B_ * N_ * DM_];
__device__ __nv_bfloat16 g_wqTh[H_ * DK_ * DM_], g_wqTl[H_ * DK_ * DM_];
__device__ __nv_bfloat16 g_wkTh[H_ * DK_ * DM_], g_wkTl[H_ * DK_ * DM_];
__device__ __nv_bfloat16 g_wvTh[H_ * DV_ * DM_], g_wvTl[H_ * DV_ * DM_];
__device__ __nv_bfloat16 g_worh[DM_ * H_ * DV_], g_worl[DM_ * H_ * DV_];
__device__ __nv_bfloat16 g_Qh [B_ * H_ * N_ * DK_], g_Ql [B_ * H_ * N_ * DK_];
__device__ __nv_bfloat16 g_Kh [B_ * H_ * N_ * DK_], g_Kl [B_ * H_ * N_ * DK_];
__device__ float         g_Sf [B_ * H_ * N_ * N_];
__device__ __nv_bfloat16 g_Sh [B_ * H_ * N_ * N_],  g_Sl [B_ * H_ * N_ * N_];
__device__ __nv_bfloat16 g_Vth[B_ * H_ * DV_ * N_], g_Vtl[B_ * H_ * DV_ * N_];
__device__ float         g_Of [B_ * H_ * N_ * DV_];
__device__ __nv_bfloat16 g_Ph [B_ * DV_ * H_ * N_], g_Pl [B_ * DV_ * H_ * N_];

// ---------------------------------------------------------------------------
// helpers
// ---------------------------------------------------------------------------
__device__ __forceinline__ uint32_t smem_u32(const void* p) {
    uint32_t a;
    asm("{ .reg .u64 t; cvta.to.shared.u64 t, %1; cvt.u32.u64 %0, t; }"
        : "=r"(a) : "l"(p));
    return a;
}

__device__ __forceinline__ void split_bf16(float x, __nv_bfloat16& h, __nv_bfloat16& l) {
    h = __float2bfloat16_rn(x);
    l = __float2bfloat16_rn(x - __bfloat162float(h));
}

__device__ __forceinline__ void cp_async16(uint32_t saddr, const void* gptr) {
    asm volatile("cp.async.cg.shared.global [%0], [%1], 16;"
                 :: "r"(saddr), "l"(gptr));
}

__device__ __forceinline__ uint32_t lds_u32(const __nv_bfloat16* p) {
    return *reinterpret_cast<const uint32_t*>(p);
}

__device__ __forceinline__ void mma_bf16(float* c,
                                         uint32_t a0, uint32_t a1, uint32_t a2, uint32_t a3,
                                         uint32_t b0, uint32_t b1)
{
    asm volatile(
        "mma.sync.aligned.m16n8k16.row.col.f32.bf16.bf16.f32 "
        "{%0,%1,%2,%3}, {%4,%5,%6,%7}, {%8,%9}, {%0,%1,%2,%3};"
        : "+f"(c[0]), "+f"(c[1]), "+f"(c[2]), "+f"(c[3])
        : "r"(a0), "r"(a1), "r"(a2), "r"(a3), "r"(b0), "r"(b1));
}

// ---------------------------------------------------------------------------
// 3xBF16 error-compensated batched GEMM:
//   C[m,n] = alpha * sum_k (Ah+Al)[m,k] * (Bh+Bl)[n,k]   (drop Al*Bl)
// A: M x K row-major (lda), B: N x K row-major (ldb), C: M x N (ldc).
// Tile 128 x BN, BK=32 bf16, 4-stage cp.async, 256 threads.
// mode 0: write fp32 C.  mode 1: write split Ch/Cl bf16.
// ---------------------------------------------------------------------------
template<int BN>
__global__ void __launch_bounds__(256)
gemm_bf16x3(const __nv_bfloat16* __restrict__ Ah, const __nv_bfloat16* __restrict__ Al,
            const __nv_bfloat16* __restrict__ Bh, const __nv_bfloat16* __restrict__ Bl,
            float* __restrict__ C,
            __nv_bfloat16* __restrict__ Ch, __nv_bfloat16* __restrict__ Cl,
            int Kdim, int lda, int ldb, int ldc,
            long long sAo, long long sAi,
            long long sBo, long long sBi,
            long long sCo, long long sCi,
            int inner, float alpha, int mode)
{
    constexpr int BM = 128, BK = 32, STAGES = 4;
    constexpr int LDB = 40;                       // padded row, bf16 units
    constexpr int AH_OFF = 0;
    constexpr int AL_OFF = BM * LDB;
    constexpr int BH_OFF = 2 * BM * LDB;
    constexpr int BL_OFF = 2 * BM * LDB + BN * LDB;
    constexpr int STG    = 2 * (BM + BN) * LDB;   // bf16 per stage
    constexpr int WM = (BN == 128) ? 2 : 4;
    constexpr int WN = 8 / WM;
    constexpr int MT = (BM / WM) / 16;            // 4 or 2
    constexpr int NT = (BN / WN) / 8;             // 4
    constexpr int A_IT = BM * 4 / 256;            // 16B chunks/thread per A array
    constexpr int B_IT = BN * 4 / 256;

    extern __shared__ __nv_bfloat16 sm[];

    const int tid  = threadIdx.x;
    const int wid  = tid >> 5;
    const int lane = tid & 31;
    const int g    = lane >> 2;
    const int t    = lane & 3;

    const int z  = blockIdx.z;
    const int zo = z / inner;
    const int zi = z - zo * inner;
    Ah += zo * sAo + zi * sAi;  Al += zo * sAo + zi * sAi;
    Bh += zo * sBo + zi * sBi;  Bl += zo * sBo + zi * sBi;
    const long long coff = zo * sCo + zi * sCi;
    const int m0 = blockIdx.y * BM;
    const int n0 = blockIdx.x * BN;

    const int wm0 = (wid % WM) * (BM / WM);
    const int wn0 = (wid / WM) * (BN / WN);

    const uint32_t sbase = smem_u32(sm);

    // per-thread cp.async mapping: chunk c -> row c>>2, 8-bf16 col (c&3)*8
    int  a_go[A_IT]; uint32_t a_sp[A_IT];
#pragma unroll
    for (int i = 0; i < A_IT; i++) {
        int c = tid + i * 256;
        int row = c >> 2, kc = (c & 3) * 8;
        a_go[i] = (m0 + row) * lda + kc;
        a_sp[i] = (uint32_t)(row * LDB + kc) * 2u;
    }
    int  b_go[B_IT]; uint32_t b_sp[B_IT];
#pragma unroll
    for (int i = 0; i < B_IT; i++) {
        int c = tid + i * 256;
        int row = c >> 2, kc = (c & 3) * 8;
        b_go[i] = (n0 + row) * ldb + kc;
        b_sp[i] = (uint32_t)(row * LDB + kc) * 2u;
    }

    const int T = Kdim / BK;

    float acc[MT][NT][4];
#pragma unroll
    for (int i = 0; i < MT; i++)
#pragma unroll
        for (int j = 0; j < NT; j++)
#pragma unroll
            for (int q = 0; q < 4; q++) acc[i][j][q] = 0.f;

    // ---- prologue ----
#pragma unroll
    for (int p = 0; p < STAGES - 1; p++) {
        if (p < T) {
            uint32_t sb = sbase + (uint32_t)((p % STAGES) * STG) * 2u;
#pragma unroll
            for (int i = 0; i < A_IT; i++) {
                cp_async16(sb + AH_OFF * 2 + a_sp[i], Ah + a_go[i] + p * BK);
                cp_async16(sb + AL_OFF * 2 + a_sp[i], Al + a_go[i] + p * BK);
            }
#pragma unroll
            for (int i = 0; i < B_IT; i++) {
                cp_async16(sb + BH_OFF * 2 + b_sp[i], Bh + b_go[i] + p * BK);
                cp_async16(sb + BL_OFF * 2 + b_sp[i], Bl + b_go[i] + p * BK);
            }
        }
        asm volatile("cp.async.commit_group;" ::: "memory");
    }

    for (int kt = 0; kt < T; kt++) {
        asm volatile("cp.async.wait_group %0;" :: "n"(STAGES - 2) : "memory");
        __syncthreads();

        {   // prefetch tile kt+STAGES-1
            int tl = kt + STAGES - 1;
            if (tl < T) {
                uint32_t sb = sbase + (uint32_t)((tl % STAGES) * STG) * 2u;
#pragma unroll
                for (int i = 0; i < A_IT; i++) {
                    cp_async16(sb + AH_OFF * 2 + a_sp[i], Ah + a_go[i] + tl * BK);
                    cp_async16(sb + AL_OFF * 2 + a_sp[i], Al + a_go[i] + tl * BK);
                }
#pragma unroll
                for (int i = 0; i < B_IT; i++) {
                    cp_async16(sb + BH_OFF * 2 + b_sp[i], Bh + b_go[i] + tl * BK);
                    cp_async16(sb + BL_OFF * 2 + b_sp[i], Bl + b_go[i] + tl * BK);
                }
            }
            asm volatile("cp.async.commit_group;" ::: "memory");
        }

        const __nv_bfloat16* st = sm + (kt % STAGES) * STG;
        const __nv_bfloat16* sB = st + BH_OFF;
#pragma unroll
        for (int kk = 0; kk < BK; kk += 16) {
            uint32_t bh[NT][2], bl[NT][2];
#pragma unroll
            for (int nt = 0; nt < NT; nt++) {
                const __nv_bfloat16* bp = sB + (wn0 + nt * 8 + g) * LDB + kk + 2 * t;
                bh[nt][0] = lds_u32(bp);
                bh[nt][1] = lds_u32(bp + 8);
                bl[nt][0] = lds_u32(bp + BN * LDB);
                bl[nt][1] = lds_u32(bp + BN * LDB + 8);
            }
#pragma unroll
            for (int mt = 0; mt < MT; mt++) {
                const __nv_bfloat16* ap = st + (wm0 + mt * 16 + g) * LDB + kk + 2 * t;
                uint32_t ah0 = lds_u32(ap);
                uint32_t ah1 = lds_u32(ap + 8 * LDB);
                uint32_t ah2 = lds_u32(ap + 8);
                uint32_t ah3 = lds_u32(ap + 8 * LDB + 8);
                const __nv_bfloat16* al = ap + AL_OFF;
                uint32_t al0 = lds_u32(al);
                uint32_t al1 = lds_u32(al + 8 * LDB);
                uint32_t al2 = lds_u32(al + 8);
                uint32_t al3 = lds_u32(al + 8 * LDB + 8);
#pragma unroll
                for (int nt = 0; nt < NT; nt++) {
                    mma_bf16(acc[mt][nt], ah0, ah1, ah2, ah3, bh[nt][0], bh[nt][1]);
                    mma_bf16(acc[mt][nt], ah0, ah1, ah2, ah3, bl[nt][0], bl[nt][1]);
                    mma_bf16(acc[mt][nt], al0, al1, al2, al3, bh[nt][0], bh[nt][1]);
                }
            }
        }
    }

    // ---- epilogue ----
#pragma unroll
    for (int mt = 0; mt < MT; mt++) {
        const int r0 = m0 + wm0 + mt * 16 + g;
#pragma unroll
        for (int nt = 0; nt < NT; nt++) {
            const int cc = n0 + wn0 + nt * 8 + 2 * t;
            float v00 = acc[mt][nt][0] * alpha, v01 = acc[mt][nt][1] * alpha;
            float v10 = acc[mt][nt][2] * alpha, v11 = acc[mt][nt][3] * alpha;
            if (mode == 0) {
                float2 u0; u0.x = v00; u0.y = v01;
                float2 u1; u1.x = v10; u1.y = v11;
                *(float2*)&C[coff + (long long)r0 * ldc + cc]       = u0;
                *(float2*)&C[coff + (long long)(r0 + 8) * ldc + cc] = u1;
            } else {
                __nv_bfloat16 h0, l0, h1, l1;
                split_bf16(v00, h0, l0); split_bf16(v01, h1, l1);
                __nv_bfloat162 hh; hh.x = h0; hh.y = h1;
                __nv_bfloat162 ll; ll.x = l0; ll.y = l1;
                *(__nv_bfloat162*)&Ch[coff + (long long)r0 * ldc + cc] = hh;
                *(__nv_bfloat162*)&Cl[coff + (long long)r0 * ldc + cc] = ll;
                split_bf16(v10, h0, l0); split_bf16(v11, h1, l1);
                hh.x = h0; hh.y = h1; ll.x = l0; ll.y = l1;
                *(__nv_bfloat162*)&Ch[coff + (long long)(r0 + 8) * ldc + cc] = hh;
                *(__nv_bfloat162*)&Cl[coff + (long long)(r0 + 8) * ldc + cc] = ll;
            }
        }
    }
}

// ---------------------------------------------------------------------------
// fp32 -> (hi, lo) bf16 split copy
// ---------------------------------------------------------------------------
__global__ void split_copy_kernel(const float4* __restrict__ in,
                                  __nv_bfloat16* __restrict__ oh,
                                  __nv_bfloat16* __restrict__ ol, int n4)
{
    int i = blockIdx.x * blockDim.x + threadIdx.x;
    if (i < n4) {
        float4 v = in[i];
        __nv_bfloat16 h, l;
        __nv_bfloat162 h01, h23, l01, l23;
        split_bf16(v.x, h, l); h01.x = h; l01.x = l;
        split_bf16(v.y, h, l); h01.y = h; l01.y = l;
        split_bf16(v.z, h, l); h23.x = h; l23.x = l;
        split_bf16(v.w, h, l); h23.y = h; l23.y = l;
        ((__nv_bfloat162*)oh)[2 * i] = h01; ((__nv_bfloat162*)oh)[2 * i + 1] = h23;
        ((__nv_bfloat162*)ol)[2 * i] = l01; ((__nv_bfloat162*)ol)[2 * i + 1] = l23;
    }
}

// ---------------------------------------------------------------------------
// Batched 32x32 transpose with bf16 hi/lo split output.
// in element (r,c) -> out element (c,r).
// ---------------------------------------------------------------------------
__global__ void transpose_split_kernel(const float* __restrict__ in,
                                       __nv_bfloat16* __restrict__ oh,
                                       __nv_bfloat16* __restrict__ ol,
                                       int ldi, int ldo,
                                       long long sIo, long long sIi,
                                       long long sOo, long long sOi, int inner)
{
    __shared__ float tile[32][33];
    const int z  = blockIdx.z;
    const int zo = z / inner, zi = z - zo * inner;
    const float* ip = in + zo * sIo + zi * sIi;
    const long long oo = zo * sOo + zi * sOi;
    const int c0 = blockIdx.x * 32, r0 = blockIdx.y * 32;
    const int tx = threadIdx.x, ty = threadIdx.y;
#pragma unroll
    for (int i = 0; i < 32; i += 8)
        tile[ty + i][tx] = ip[(long long)(r0 + ty + i) * ldi + c0 + tx];
    __syncthreads();
#pragma unroll
    for (int i = 0; i < 32; i += 8) {
        float v = tile[tx][ty + i];
        __nv_bfloat16 h, l;
        split_bf16(v, h, l);
        long long o = oo + (long long)(c0 + ty + i) * ldo + r0 + tx;
        oh[o] = h; ol[o] = l;
    }
}

// ---------------------------------------------------------------------------
// Row softmax: fp32 in, bf16 hi/lo out. One block per 1024-wide row.
// ---------------------------------------------------------------------------
__global__ void softmax_split_kernel(const float* __restrict__ Sf,
                                     __nv_bfloat16* __restrict__ Sh,
                                     __nv_bfloat16* __restrict__ Sl)
{
    __shared__ float red[8];
    const long long row = (long long)blockIdx.x * N_;
    const float4* p = (const float4*)(Sf + row);
    const int tid  = threadIdx.x;
    const int lane = tid & 31;
    const int warp = tid >> 5;

    float4 x = p[tid];

    float m = fmaxf(fmaxf(x.x, x.y), fmaxf(x.z, x.w));
#pragma unroll
    for (int o = 16; o; o >>= 1) m = fmaxf(m, __shfl_xor_sync(0xffffffffu, m, o));
    if (lane == 0) red[warp] = m;
    __syncthreads();
    m = red[0];
#pragma unroll
    for (int j = 1; j < 8; j++) m = fmaxf(m, red[j]);
    __syncthreads();

    x.x = __expf(x.x - m); x.y = __expf(x.y - m);
    x.z = __expf(x.z - m); x.w = __expf(x.w - m);
    float s = x.x + x.y + x.z + x.w;
#pragma unroll
    for (int o = 16; o; o >>= 1) s += __shfl_xor_sync(0xffffffffu, s, o);
    if (lane == 0) red[warp] = s;
    __syncthreads();
    s = red[0];
#pragma unroll
    for (int j = 1; j < 8; j++) s += red[j];

    const float inv = 1.0f / s;
    __nv_bfloat16 h, l;
    __nv_bfloat162 h01, h23, l01, l23;
    split_bf16(x.x * inv, h, l); h01.x = h; l01.x = l;
    split_bf16(x.y * inv, h, l); h01.y = h; l01.y = l;
    split_bf16(x.z * inv, h, l); h23.x = h; l23.x = l;
    split_bf16(x.w * inv, h, l); h23.y = h; l23.y = l;
    ((__nv_bfloat162*)(Sh + row))[2 * tid]     = h01;
    ((__nv_bfloat162*)(Sh + row))[2 * tid + 1] = h23;
    ((__nv_bfloat162*)(Sl + row))[2 * tid]     = l01;
    ((__nv_bfloat162*)(Sl + row))[2 * tid + 1] = l23;
}

// ---------------------------------------------------------------------------
// Launch
// ---------------------------------------------------------------------------
extern "C" void kernel_launch(void* const* d_in, const int* in_sizes, int n_in,
                              void* d_out, int out_size)
{
    (void)in_sizes; (void)n_in; (void)out_size;

    const float* query = (const float*)d_in[0];
    const float* key   = (const float*)d_in[1];
    const float* value = (const float*)d_in[2];
    const float* w_q   = (const float*)d_in[3];
    const float* w_k   = (const float*)d_in[4];
    const float* w_v   = (const float*)d_in[5];
    const float* w_o   = (const float*)d_in[6];
    float*       out   = (float*)d_out;

    __nv_bfloat16 *qh, *ql, *kh, *kl, *vh, *vl;
    __nv_bfloat16 *wqTh, *wqTl, *wkTh, *wkTl, *wvTh, *wvTl, *worh, *worl;
    __nv_bfloat16 *Qh, *Ql, *Kh, *Kl, *Sh, *Sl, *Vth, *Vtl, *Ph, *Pl;
    float *Sf, *Of;
    cudaGetSymbolAddress((void**)&qh, g_qh);   cudaGetSymbolAddress((void**)&ql, g_ql);
    cudaGetSymbolAddress((void**)&kh, g_kh);   cudaGetSymbolAddress((void**)&kl, g_kl);
    cudaGetSymbolAddress((void**)&vh, g_vh);   cudaGetSymbolAddress((void**)&vl, g_vl);
    cudaGetSymbolAddress((void**)&wqTh, g_wqTh); cudaGetSymbolAddress((void**)&wqTl, g_wqTl);
    cudaGetSymbolAddress((void**)&wkTh, g_wkTh); cudaGetSymbolAddress((void**)&wkTl, g_wkTl);
    cudaGetSymbolAddress((void**)&wvTh, g_wvTh); cudaGetSymbolAddress((void**)&wvTl, g_wvTl);
    cudaGetSymbolAddress((void**)&worh, g_worh); cudaGetSymbolAddress((void**)&worl, g_worl);
    cudaGetSymbolAddress((void**)&Qh, g_Qh);   cudaGetSymbolAddress((void**)&Ql, g_Ql);
    cudaGetSymbolAddress((void**)&Kh, g_Kh);   cudaGetSymbolAddress((void**)&Kl, g_Kl);
    cudaGetSymbolAddress((void**)&Sf, g_Sf);
    cudaGetSymbolAddress((void**)&Sh, g_Sh);   cudaGetSymbolAddress((void**)&Sl, g_Sl);
    cudaGetSymbolAddress((void**)&Vth, g_Vth); cudaGetSymbolAddress((void**)&Vtl, g_Vtl);
    cudaGetSymbolAddress((void**)&Of, g_Of);
    cudaGetSymbolAddress((void**)&Ph, g_Ph);   cudaGetSymbolAddress((void**)&Pl, g_Pl);

    // dyn smem: 4 stages * 2*(BM+BN)*40 bf16 * 2B
    constexpr int SMEM_128 = 4 * 2 * (128 + 128) * 40 * 2;  // 163840
    constexpr int SMEM_64  = 4 * 2 * (128 + 64)  * 40 * 2;  // 122880
    cudaFuncSetAttribute(gemm_bf16x3<128>, cudaFuncAttributeMaxDynamicSharedMemorySize, SMEM_128);
    cudaFuncSetAttribute(gemm_bf16x3<64>,  cudaFuncAttributeMaxDynamicSharedMemorySize, SMEM_64);

    const long long MB = 1024LL * 1024LL;
    const int ZBH = B_ * H_;

    // ---- 0. split inputs into bf16 hi/lo
    split_copy_kernel<<<(B_ * N_ * DM_ / 4 + 255) / 256, 256>>>((const float4*)query, qh, ql, B_ * N_ * DM_ / 4);
    split_copy_kernel<<<(B_ * N_ * DM_ / 4 + 255) / 256, 256>>>((const float4*)key,   kh, kl, B_ * N_ * DM_ / 4);
    split_copy_kernel<<<(B_ * N_ * DM_ / 4 + 255) / 256, 256>>>((const float4*)value, vh, vl, B_ * N_ * DM_ / 4);
    split_copy_kernel<<<(DM_ * H_ * DV_ / 4 + 255) / 256, 256>>>((const float4*)w_o,  worh, worl, DM_ * H_ * DV_ / 4);

    // ---- 0b. transpose+split weights: [h][d][x] -> [h][x][d]
    transpose_split_kernel<<<dim3(DK_ / 32, DM_ / 32, H_), dim3(32, 8)>>>(
        w_q, wqTh, wqTl, DK_, DM_, (long long)DM_ * DK_, 0, (long long)DK_ * DM_, 0, 1);
    transpose_split_kernel<<<dim3(DK_ / 32, DM_ / 32, H_), dim3(32, 8)>>>(
        w_k, wkTh, wkTl, DK_, DM_, (long long)DM_ * DK_, 0, (long long)DK_ * DM_, 0, 1);
    transpose_split_kernel<<<dim3(DV_ / 32, DM_ / 32, H_), dim3(32, 8)>>>(
        w_v, wvTh, wvTl, DV_, DM_, (long long)DM_ * DV_, 0, (long long)DV_ * DM_, 0, 1);

    // ---- 1. Q = q @ wqT^T : per (b,h)  M=1024 N=64 K=1024  -> split
    gemm_bf16x3<64><<<dim3(1, 8, ZBH), 256, SMEM_64>>>(
        qh, ql, wqTh, wqTl, nullptr, Qh, Ql,
        DM_, DM_, DM_, DK_,
        (long long)N_ * DM_, 0,
        0, (long long)DK_ * DM_,
        (long long)H_ * N_ * DK_, (long long)N_ * DK_,
        H_, 1.0f, 1);

    // ---- 2. K projection -> split
    gemm_bf16x3<64><<<dim3(1, 8, ZBH), 256, SMEM_64>>>(
        kh, kl, wkTh, wkTl, nullptr, Kh, Kl,
        DM_, DM_, DM_, DK_,
        (long long)N_ * DM_, 0,
        0, (long long)DK_ * DM_,
        (long long)H_ * N_ * DK_, (long long)N_ * DK_,
        H_, 1.0f, 1);

    // ---- 3. scores = (Q @ K^T)/8 : per z  M=1024 N=1024 K=64 -> fp32
    gemm_bf16x3<128><<<dim3(8, 8, ZBH), 256, SMEM_128>>>(
        Qh, Ql, Kh, Kl, Sf, nullptr, nullptr,
        DK_, DK_, DK_, N_,
        (long long)N_ * DK_, 0,
        (long long)N_ * DK_, 0,
        (long long)N_ * N_, 0,
        1, 0.125f, 0);

    // ---- 4. softmax rows -> split S
    softmax_split_kernel<<<ZBH * N_, 256>>>(Sf, Sh, Sl);

    // ---- 5. Vt[v,m] = sum_d wvT[h][v,d] * v[b][m,d] : M=N=K=1024 -> split
    gemm_bf16x3<128><<<dim3(8, 8, ZBH), 256, SMEM_128>>>(
        wvTh, wvTl, vh, vl, nullptr, Vth, Vtl,
        DM_, DM_, DM_, N_,
        0, (long long)DV_ * DM_,
        (long long)N_ * DM_, 0,
        (long long)H_ * DV_ * N_, (long long)DV_ * N_,
        H_, 1.0f, 1);

    // ---- 6. O[q,v] = sum_m S[q,m] * Vt[v,m] : M=N=K=1024 -> fp32
    gemm_bf16x3<128><<<dim3(8, 8, ZBH), 256, SMEM_128>>>(
        Sh, Sl, Vth, Vtl, Of, nullptr, nullptr,
        N_, N_, N_, DV_,
        (long long)N_ * N_, 0,
        (long long)DV_ * N_, 0,
        (long long)N_ * DV_, 0,
        1, 1.0f, 0);

    // ---- 7. permute O[b,h,q,v] -> P[b][v][h*N+q], split
    transpose_split_kernel<<<dim3(32, 32, ZBH), dim3(32, 8)>>>(
        Of, Ph, Pl, DV_, H_ * N_,
        (long long)H_ * MB, MB,
        (long long)H_ * MB, (long long)N_,
        H_);

    // ---- 8. out[b][d,v] = sum_e wor[d,e] * P[b][v,e] : M=N=1024 K=16384
    gemm_bf16x3<128><<<dim3(8, 8, B_), 256, SMEM_128>>>(
        worh, worl, Ph, Pl, out, nullptr, nullptr,
        H_ * N_, H_ * N_, H_ * N_, DV_,
        0, 0,
        (long long)DV_ * H_ * N_, 0,
        (long long)DM_ * DV_, 0,
        1, 1.0f, 0);
}

// round 5
// speedup vs baseline: 2.3610x; 1.0998x over previous
#include <cuda_runtime.h>
#include <cuda_bf16.h>
#include <cstdint>

// ---------------------------------------------------------------------------
// Problem constants
// ---------------------------------------------------------------------------
#define B_   4
#define N_   1024
#define DM_  1024
#define H_   16
#define DK_  64
#define DV_  1024

// ---------------------------------------------------------------------------
// Scratch (device globals; no allocations allowed). hi/lo bf16 split pairs.
// ---------------------------------------------------------------------------
__device__ __nv_bfloat16 g_qh [B_ * N_ * DM_],  g_ql [B_ * N_ * DM_];
__device__ __nv_bfloat16 g_kh [B_ * N_ * DM_],  g_kl [B_ * N_ * DM_];
__device__ __nv_bfloat16 g_vh [B_ * N_ * DM_],  g_vl [B_ * N_ * DM_];
__device__ __nv_bfloat16 g_wqTh[H_ * DK_ * DM_], g_wqTl[H_ * DK_ * DM_];
__device__ __nv_bfloat16 g_wkTh[H_ * DK_ * DM_], g_wkTl[H_ * DK_ * DM_];
__device__ __nv_bfloat16 g_wvTh[H_ * DV_ * DM_], g_wvTl[H_ * DV_ * DM_];
__device__ __nv_bfloat16 g_worh[DM_ * H_ * DV_], g_worl[DM_ * H_ * DV_];
__device__ __nv_bfloat16 g_Qh [B_ * H_ * N_ * DK_], g_Ql [B_ * H_ * N_ * DK_];
__device__ __nv_bfloat16 g_Kh [B_ * H_ * N_ * DK_], g_Kl [B_ * H_ * N_ * DK_];
__device__ float         g_Sf [B_ * H_ * N_ * N_];
__device__ __nv_bfloat16 g_Sh [B_ * H_ * N_ * N_],  g_Sl [B_ * H_ * N_ * N_];
__device__ __nv_bfloat16 g_Vth[B_ * H_ * DV_ * N_], g_Vtl[B_ * H_ * DV_ * N_];
__device__ float         g_Of [B_ * H_ * N_ * DV_];
__device__ __nv_bfloat16 g_Ph [B_ * DV_ * H_ * N_], g_Pl [B_ * DV_ * H_ * N_];

// ---------------------------------------------------------------------------
// helpers
// ---------------------------------------------------------------------------
__device__ __forceinline__ uint32_t smem_u32(const void* p) {
    uint32_t a;
    asm("{ .reg .u64 t; cvta.to.shared.u64 t, %1; cvt.u32.u64 %0, t; }"
        : "=r"(a) : "l"(p));
    return a;
}

__device__ __forceinline__ void split_bf16(float x, __nv_bfloat16& h, __nv_bfloat16& l) {
    h = __float2bfloat16_rn(x);
    l = __float2bfloat16_rn(x - __bfloat162float(h));
}

__device__ __forceinline__ void cp_async16(uint32_t saddr, const void* gptr) {
    asm volatile("cp.async.cg.shared.global [%0], [%1], 16;"
                 :: "r"(saddr), "l"(gptr));
}

__device__ __forceinline__ uint32_t lds_u32(const __nv_bfloat16* p) {
    return *reinterpret_cast<const uint32_t*>(p);
}

__device__ __forceinline__ void mma_bf16(float* c,
                                         uint32_t a0, uint32_t a1, uint32_t a2, uint32_t a3,
                                         uint32_t b0, uint32_t b1)
{
    asm volatile(
        "mma.sync.aligned.m16n8k16.row.col.f32.bf16.bf16.f32 "
        "{%0,%1,%2,%3}, {%4,%5,%6,%7}, {%8,%9}, {%0,%1,%2,%3};"
        : "+f"(c[0]), "+f"(c[1]), "+f"(c[2]), "+f"(c[3])
        : "r"(a0), "r"(a1), "r"(a2), "r"(a3), "r"(b0), "r"(b1));
}

#define LDSM4(r, addr) \
    asm volatile("ldmatrix.sync.aligned.m8n8.x4.shared.b16 {%0,%1,%2,%3}, [%4];" \
        : "=r"((r)[0]), "=r"((r)[1]), "=r"((r)[2]), "=r"((r)[3]) : "r"(addr))

// ===========================================================================
// WIDE 3xBF16 GEMM: CTA tile 128 x 256, warp tile 64 x 64, ldmatrix loads.
//   C[m,n] = alpha * sum_k (Ah+Al)[m,k]*(Bh+Bl)[n,k]   (Al*Bl dropped)
// A: M x K row-major (lda), B: N x K row-major (ldb), C: M x N (ldc).
// BK=32, 3-stage cp.async pipeline, 256 threads.
// mode 0: fp32 C.   mode 1: split Ch/Cl bf16.
// ===========================================================================
__global__ void __launch_bounds__(256, 1)
gemm_bf16x3_wide(const __nv_bfloat16* __restrict__ Ah, const __nv_bfloat16* __restrict__ Al,
                 const __nv_bfloat16* __restrict__ Bh, const __nv_bfloat16* __restrict__ Bl,
                 float* __restrict__ C,
                 __nv_bfloat16* __restrict__ Ch, __nv_bfloat16* __restrict__ Cl,
                 int Kdim, int lda, int ldb, int ldc,
                 long long sAo, long long sAi,
                 long long sBo, long long sBi,
                 long long sCo, long long sCi,
                 int inner, float alpha, int mode)
{
    constexpr int BM = 128, BN = 256, BK = 32, STAGES = 3;
    constexpr int LDB = 40;                         // bf16 units; 80 B row stride
    constexpr int AH_OFF = 0;
    constexpr int AL_OFF = BM * LDB;
    constexpr int BH_OFF = 2 * BM * LDB;
    constexpr int BL_OFF = 2 * BM * LDB + BN * LDB;
    constexpr int STG    = 2 * (BM + BN) * LDB;     // 30720 bf16 = 61440 B
    constexpr int MT = 4;                           // 64/16
    constexpr int NPAIR = 4;                        // 64/16 (2 n8 per pair)
    constexpr int A_IT = BM * 4 / 256;              // 2 chunks/thread/array
    constexpr int B_IT = BN * 4 / 256;              // 4

    extern __shared__ __nv_bfloat16 sm[];

    const int tid  = threadIdx.x;
    const int wid  = tid >> 5;
    const int lane = tid & 31;
    const int g    = lane >> 2;
    const int t    = lane & 3;

    const int z  = blockIdx.z;
    const int zo = z / inner;
    const int zi = z - zo * inner;
    Ah += zo * sAo + zi * sAi;  Al += zo * sAo + zi * sAi;
    Bh += zo * sBo + zi * sBi;  Bl += zo * sBo + zi * sBi;
    const long long coff = zo * sCo + zi * sCi;
    const int m0 = blockIdx.y * BM;
    const int n0 = blockIdx.x * BN;

    const int wm0 = (wid & 1) * 64;     // warp grid 2 x 4
    const int wn0 = (wid >> 1) * 64;

    const uint32_t sbase = smem_u32(sm);

    // ldmatrix per-lane byte offsets (within the hi arrays)
    const int q = lane >> 3;
    const uint32_t a_lane = (uint32_t)(((q & 1) * 8 + (lane & 7)) * LDB * 2 + (q >> 1) * 16);
    const uint32_t b_lane = (uint32_t)(((q >> 1) * 8 + (lane & 7)) * LDB * 2 + (q & 1) * 16);

    // cp.async mapping: chunk c -> row c>>2, 8-bf16 col (c&3)*8
    int  a_go[A_IT]; uint32_t a_sp[A_IT];
#pragma unroll
    for (int i = 0; i < A_IT; i++) {
        int c = tid + i * 256;
        int row = c >> 2, kc = (c & 3) * 8;
        a_go[i] = (m0 + row) * lda + kc;
        a_sp[i] = (uint32_t)(row * LDB + kc) * 2u;
    }
    int  b_go[B_IT]; uint32_t b_sp[B_IT];
#pragma unroll
    for (int i = 0; i < B_IT; i++) {
        int c = tid + i * 256;
        int row = c >> 2, kc = (c & 3) * 8;
        b_go[i] = (n0 + row) * ldb + kc;
        b_sp[i] = (uint32_t)(row * LDB + kc) * 2u;
    }

    const int T = Kdim / BK;

    float acc[MT][8][4];
#pragma unroll
    for (int i = 0; i < MT; i++)
#pragma unroll
        for (int j = 0; j < 8; j++)
#pragma unroll
            for (int r = 0; r < 4; r++) acc[i][j][r] = 0.f;

    // ---- prologue ----
#pragma unroll
    for (int p = 0; p < STAGES - 1; p++) {
        if (p < T) {
            uint32_t sb = sbase + (uint32_t)((p % STAGES) * STG) * 2u;
#pragma unroll
            for (int i = 0; i < A_IT; i++) {
                cp_async16(sb + AH_OFF * 2 + a_sp[i], Ah + a_go[i] + p * BK);
                cp_async16(sb + AL_OFF * 2 + a_sp[i], Al + a_go[i] + p * BK);
            }
#pragma unroll
            for (int i = 0; i < B_IT; i++) {
                cp_async16(sb + BH_OFF * 2 + b_sp[i], Bh + b_go[i] + p * BK);
                cp_async16(sb + BL_OFF * 2 + b_sp[i], Bl + b_go[i] + p * BK);
            }
        }
        asm volatile("cp.async.commit_group;" ::: "memory");
    }

    for (int kt = 0; kt < T; kt++) {
        asm volatile("cp.async.wait_group %0;" :: "n"(STAGES - 2) : "memory");
        __syncthreads();

        {   // prefetch tile kt+STAGES-1 (overwrites stage of kt-1; barrier above protects)
            int tl = kt + STAGES - 1;
            if (tl < T) {
                uint32_t sb = sbase + (uint32_t)((tl % STAGES) * STG) * 2u;
#pragma unroll
                for (int i = 0; i < A_IT; i++) {
                    cp_async16(sb + AH_OFF * 2 + a_sp[i], Ah + a_go[i] + tl * BK);
                    cp_async16(sb + AL_OFF * 2 + a_sp[i], Al + a_go[i] + tl * BK);
                }
#pragma unroll
                for (int i = 0; i < B_IT; i++) {
                    cp_async16(sb + BH_OFF * 2 + b_sp[i], Bh + b_go[i] + tl * BK);
                    cp_async16(sb + BL_OFF * 2 + b_sp[i], Bl + b_go[i] + tl * BK);
                }
            }
            asm volatile("cp.async.commit_group;" ::: "memory");
        }

        const uint32_t stg = sbase + (uint32_t)((kt % STAGES) * STG) * 2u;
#pragma unroll
        for (int kk = 0; kk < BK; kk += 16) {
            // A fragments (hi + lo) via ldmatrix.x4
            uint32_t ah[MT][4], al[MT][4];
#pragma unroll
            for (int mt = 0; mt < MT; mt++) {
                uint32_t aa = stg + a_lane + (uint32_t)((wm0 + mt * 16) * LDB + kk) * 2u;
                LDSM4(ah[mt], aa);
                LDSM4(al[mt], aa + (uint32_t)(AL_OFF * 2));
            }
#pragma unroll
            for (int pr = 0; pr < NPAIR; pr++) {
                uint32_t bh4[4], bl4[4];
                uint32_t ba = stg + (uint32_t)(BH_OFF * 2) + b_lane
                            + (uint32_t)((wn0 + pr * 16) * LDB + kk) * 2u;
                LDSM4(bh4, ba);
                LDSM4(bl4, ba + (uint32_t)(BN * LDB * 2));
                const int nt0 = pr * 2, nt1 = pr * 2 + 1;
#pragma unroll
                for (int mt = 0; mt < MT; mt++) {
                    mma_bf16(acc[mt][nt0], ah[mt][0], ah[mt][1], ah[mt][2], ah[mt][3], bh4[0], bh4[1]);
                    mma_bf16(acc[mt][nt0], ah[mt][0], ah[mt][1], ah[mt][2], ah[mt][3], bl4[0], bl4[1]);
                    mma_bf16(acc[mt][nt0], al[mt][0], al[mt][1], al[mt][2], al[mt][3], bh4[0], bh4[1]);
                    mma_bf16(acc[mt][nt1], ah[mt][0], ah[mt][1], ah[mt][2], ah[mt][3], bh4[2], bh4[3]);
                    mma_bf16(acc[mt][nt1], ah[mt][0], ah[mt][1], ah[mt][2], ah[mt][3], bl4[2], bl4[3]);
                    mma_bf16(acc[mt][nt1], al[mt][0], al[mt][1], al[mt][2], al[mt][3], bh4[2], bh4[3]);
                }
            }
        }
    }

    // ---- epilogue ----
#pragma unroll
    for (int mt = 0; mt < MT; mt++) {
        const int r0 = m0 + wm0 + mt * 16 + g;
#pragma unroll
        for (int nt = 0; nt < 8; nt++) {
            const int cc = n0 + wn0 + nt * 8 + 2 * t;
            float v00 = acc[mt][nt][0] * alpha, v01 = acc[mt][nt][1] * alpha;
            float v10 = acc[mt][nt][2] * alpha, v11 = acc[mt][nt][3] * alpha;
            if (mode == 0) {
                float2 u0; u0.x = v00; u0.y = v01;
                float2 u1; u1.x = v10; u1.y = v11;
                *(float2*)&C[coff + (long long)r0 * ldc + cc]       = u0;
                *(float2*)&C[coff + (long long)(r0 + 8) * ldc + cc] = u1;
            } else {
                __nv_bfloat16 h0, l0, h1, l1;
                split_bf16(v00, h0, l0); split_bf16(v01, h1, l1);
                __nv_bfloat162 hh; hh.x = h0; hh.y = h1;
                __nv_bfloat162 ll; ll.x = l0; ll.y = l1;
                *(__nv_bfloat162*)&Ch[coff + (long long)r0 * ldc + cc] = hh;
                *(__nv_bfloat162*)&Cl[coff + (long long)r0 * ldc + cc] = ll;
                split_bf16(v10, h0, l0); split_bf16(v11, h1, l1);
                hh.x = h0; hh.y = h1; ll.x = l0; ll.y = l1;
                *(__nv_bfloat162*)&Ch[coff + (long long)(r0 + 8) * ldc + cc] = hh;
                *(__nv_bfloat162*)&Cl[coff + (long long)(r0 + 8) * ldc + cc] = ll;
            }
        }
    }
}

// ===========================================================================
// Narrow 3xBF16 GEMM (BN=64) — unchanged from R4, used for Q/K projections.
// ===========================================================================
template<int BN>
__global__ void __launch_bounds__(256)
gemm_bf16x3(const __nv_bfloat16* __restrict__ Ah, const __nv_bfloat16* __restrict__ Al,
            const __nv_bfloat16* __restrict__ Bh, const __nv_bfloat16* __restrict__ Bl,
            float* __restrict__ C,
            __nv_bfloat16* __restrict__ Ch, __nv_bfloat16* __restrict__ Cl,
            int Kdim, int lda, int ldb, int ldc,
            long long sAo, long long sAi,
            long long sBo, long long sBi,
            long long sCo, long long sCi,
            int inner, float alpha, int mode)
{
    constexpr int BM = 128, BK = 32, STAGES = 4;
    constexpr int LDB = 40;
    constexpr int AH_OFF = 0;
    constexpr int AL_OFF = BM * LDB;
    constexpr int BH_OFF = 2 * BM * LDB;
    constexpr int BL_OFF = 2 * BM * LDB + BN * LDB;
    constexpr int STG    = 2 * (BM + BN) * LDB;
    constexpr int WM = (BN == 128) ? 2 : 4;
    constexpr int WN = 8 / WM;
    constexpr int MT = (BM / WM) / 16;
    constexpr int NT = (BN / WN) / 8;
    constexpr int A_IT = BM * 4 / 256;
    constexpr int B_IT = BN * 4 / 256;

    extern __shared__ __nv_bfloat16 sm[];

    const int tid  = threadIdx.x;
    const int wid  = tid >> 5;
    const int lane = tid & 31;
    const int g    = lane >> 2;
    const int t    = lane & 3;

    const int z  = blockIdx.z;
    const int zo = z / inner;
    const int zi = z - zo * inner;
    Ah += zo * sAo + zi * sAi;  Al += zo * sAo + zi * sAi;
    Bh += zo * sBo + zi * sBi;  Bl += zo * sBo + zi * sBi;
    const long long coff = zo * sCo + zi * sCi;
    const int m0 = blockIdx.y * BM;
    const int n0 = blockIdx.x * BN;

    const int wm0 = (wid % WM) * (BM / WM);
    const int wn0 = (wid / WM) * (BN / WN);

    const uint32_t sbase = smem_u32(sm);

    int  a_go[A_IT]; uint32_t a_sp[A_IT];
#pragma unroll
    for (int i = 0; i < A_IT; i++) {
        int c = tid + i * 256;
        int row = c >> 2, kc = (c & 3) * 8;
        a_go[i] = (m0 + row) * lda + kc;
        a_sp[i] = (uint32_t)(row * LDB + kc) * 2u;
    }
    int  b_go[B_IT]; uint32_t b_sp[B_IT];
#pragma unroll
    for (int i = 0; i < B_IT; i++) {
        int c = tid + i * 256;
        int row = c >> 2, kc = (c & 3) * 8;
        b_go[i] = (n0 + row) * ldb + kc;
        b_sp[i] = (uint32_t)(row * LDB + kc) * 2u;
    }

    const int T = Kdim / BK;

    float acc[MT][NT][4];
#pragma unroll
    for (int i = 0; i < MT; i++)
#pragma unroll
        for (int j = 0; j < NT; j++)
#pragma unroll
            for (int r = 0; r < 4; r++) acc[i][j][r] = 0.f;

#pragma unroll
    for (int p = 0; p < STAGES - 1; p++) {
        if (p < T) {
            uint32_t sb = sbase + (uint32_t)((p % STAGES) * STG) * 2u;
#pragma unroll
            for (int i = 0; i < A_IT; i++) {
                cp_async16(sb + AH_OFF * 2 + a_sp[i], Ah + a_go[i] + p * BK);
                cp_async16(sb + AL_OFF * 2 + a_sp[i], Al + a_go[i] + p * BK);
            }
#pragma unroll
            for (int i = 0; i < B_IT; i++) {
                cp_async16(sb + BH_OFF * 2 + b_sp[i], Bh + b_go[i] + p * BK);
                cp_async16(sb + BL_OFF * 2 + b_sp[i], Bl + b_go[i] + p * BK);
            }
        }
        asm volatile("cp.async.commit_group;" ::: "memory");
    }

    for (int kt = 0; kt < T; kt++) {
        asm volatile("cp.async.wait_group %0;" :: "n"(STAGES - 2) : "memory");
        __syncthreads();

        {
            int tl = kt + STAGES - 1;
            if (tl < T) {
                uint32_t sb = sbase + (uint32_t)((tl % STAGES) * STG) * 2u;
#pragma unroll
                for (int i = 0; i < A_IT; i++) {
                    cp_async16(sb + AH_OFF * 2 + a_sp[i], Ah + a_go[i] + tl * BK);
                    cp_async16(sb + AL_OFF * 2 + a_sp[i], Al + a_go[i] + tl * BK);
                }
#pragma unroll
                for (int i = 0; i < B_IT; i++) {
                    cp_async16(sb + BH_OFF * 2 + b_sp[i], Bh + b_go[i] + tl * BK);
                    cp_async16(sb + BL_OFF * 2 + b_sp[i], Bl + b_go[i] + tl * BK);
                }
            }
            asm volatile("cp.async.commit_group;" ::: "memory");
        }

        const __nv_bfloat16* st = sm + (kt % STAGES) * STG;
        const __nv_bfloat16* sB = st + BH_OFF;
#pragma unroll
        for (int kk = 0; kk < BK; kk += 16) {
            uint32_t bh[NT][2], bl[NT][2];
#pragma unroll
            for (int nt = 0; nt < NT; nt++) {
                const __nv_bfloat16* bp = sB + (wn0 + nt * 8 + g) * LDB + kk + 2 * t;
                bh[nt][0] = lds_u32(bp);
                bh[nt][1] = lds_u32(bp + 8);
                bl[nt][0] = lds_u32(bp + BN * LDB);
                bl[nt][1] = lds_u32(bp + BN * LDB + 8);
            }
#pragma unroll
            for (int mt = 0; mt < MT; mt++) {
                const __nv_bfloat16* ap = st + (wm0 + mt * 16 + g) * LDB + kk + 2 * t;
                uint32_t ah0 = lds_u32(ap);
                uint32_t ah1 = lds_u32(ap + 8 * LDB);
                uint32_t ah2 = lds_u32(ap + 8);
                uint32_t ah3 = lds_u32(ap + 8 * LDB + 8);
                const __nv_bfloat16* alp = ap + AL_OFF;
                uint32_t al0 = lds_u32(alp);
                uint32_t al1 = lds_u32(alp + 8 * LDB);
                uint32_t al2 = lds_u32(alp + 8);
                uint32_t al3 = lds_u32(alp + 8 * LDB + 8);
#pragma unroll
                for (int nt = 0; nt < NT; nt++) {
                    mma_bf16(acc[mt][nt], ah0, ah1, ah2, ah3, bh[nt][0], bh[nt][1]);
                    mma_bf16(acc[mt][nt], ah0, ah1, ah2, ah3, bl[nt][0], bl[nt][1]);
                    mma_bf16(acc[mt][nt], al0, al1, al2, al3, bh[nt][0], bh[nt][1]);
                }
            }
        }
    }

#pragma unroll
    for (int mt = 0; mt < MT; mt++) {
        const int r0 = m0 + wm0 + mt * 16 + g;
#pragma unroll
        for (int nt = 0; nt < NT; nt++) {
            const int cc = n0 + wn0 + nt * 8 + 2 * t;
            float v00 = acc[mt][nt][0] * alpha, v01 = acc[mt][nt][1] * alpha;
            float v10 = acc[mt][nt][2] * alpha, v11 = acc[mt][nt][3] * alpha;
            if (mode == 0) {
                float2 u0; u0.x = v00; u0.y = v01;
                float2 u1; u1.x = v10; u1.y = v11;
                *(float2*)&C[coff + (long long)r0 * ldc + cc]       = u0;
                *(float2*)&C[coff + (long long)(r0 + 8) * ldc + cc] = u1;
            } else {
                __nv_bfloat16 h0, l0, h1, l1;
                split_bf16(v00, h0, l0); split_bf16(v01, h1, l1);
                __nv_bfloat162 hh; hh.x = h0; hh.y = h1;
                __nv_bfloat162 ll; ll.x = l0; ll.y = l1;
                *(__nv_bfloat162*)&Ch[coff + (long long)r0 * ldc + cc] = hh;
                *(__nv_bfloat162*)&Cl[coff + (long long)r0 * ldc + cc] = ll;
                split_bf16(v10, h0, l0); split_bf16(v11, h1, l1);
                hh.x = h0; hh.y = h1; ll.x = l0; ll.y = l1;
                *(__nv_bfloat162*)&Ch[coff + (long long)(r0 + 8) * ldc + cc] = hh;
                *(__nv_bfloat162*)&Cl[coff + (long long)(r0 + 8) * ldc + cc] = ll;
            }
        }
    }
}

// ---------------------------------------------------------------------------
// fp32 -> (hi, lo) bf16 split copy
// ---------------------------------------------------------------------------
__global__ void split_copy_kernel(const float4* __restrict__ in,
                                  __nv_bfloat16* __restrict__ oh,
                                  __nv_bfloat16* __restrict__ ol, int n4)
{
    int i = blockIdx.x * blockDim.x + threadIdx.x;
    if (i < n4) {
        float4 v = in[i];
        __nv_bfloat16 h, l;
        __nv_bfloat162 h01, h23, l01, l23;
        split_bf16(v.x, h, l); h01.x = h; l01.x = l;
        split_bf16(v.y, h, l); h01.y = h; l01.y = l;
        split_bf16(v.z, h, l); h23.x = h; l23.x = l;
        split_bf16(v.w, h, l); h23.y = h; l23.y = l;
        ((__nv_bfloat162*)oh)[2 * i] = h01; ((__nv_bfloat162*)oh)[2 * i + 1] = h23;
        ((__nv_bfloat162*)ol)[2 * i] = l01; ((__nv_bfloat162*)ol)[2 * i + 1] = l23;
    }
}

// ---------------------------------------------------------------------------
// Batched 32x32 transpose with bf16 hi/lo split output.
// ---------------------------------------------------------------------------
__global__ void transpose_split_kernel(const float* __restrict__ in,
                                       __nv_bfloat16* __restrict__ oh,
                                       __nv_bfloat16* __restrict__ ol,
                                       int ldi, int ldo,
                                       long long sIo, long long sIi,
                                       long long sOo, long long sOi, int inner)
{
    __shared__ float tile[32][33];
    const int z  = blockIdx.z;
    const int zo = z / inner, zi = z - zo * inner;
    const float* ip = in + zo * sIo + zi * sIi;
    const long long oo = zo * sOo + zi * sOi;
    const int c0 = blockIdx.x * 32, r0 = blockIdx.y * 32;
    const int tx = threadIdx.x, ty = threadIdx.y;
#pragma unroll
    for (int i = 0; i < 32; i += 8)
        tile[ty + i][tx] = ip[(long long)(r0 + ty + i) * ldi + c0 + tx];
    __syncthreads();
#pragma unroll
    for (int i = 0; i < 32; i += 8) {
        float v = tile[tx][ty + i];
        __nv_bfloat16 h, l;
        split_bf16(v, h, l);
        long long o = oo + (long long)(c0 + ty + i) * ldo + r0 + tx;
        oh[o] = h; ol[o] = l;
    }
}

// ---------------------------------------------------------------------------
// Row softmax: fp32 in, bf16 hi/lo out. One block per 1024-wide row.
// ---------------------------------------------------------------------------
__global__ void softmax_split_kernel(const float* __restrict__ Sf,
                                     __nv_bfloat16* __restrict__ Sh,
                                     __nv_bfloat16* __restrict__ Sl)
{
    __shared__ float red[8];
    const long long row = (long long)blockIdx.x * N_;
    const float4* p = (const float4*)(Sf + row);
    const int tid  = threadIdx.x;
    const int lane = tid & 31;
    const int warp = tid >> 5;

    float4 x = p[tid];

    float m = fmaxf(fmaxf(x.x, x.y), fmaxf(x.z, x.w));
#pragma unroll
    for (int o = 16; o; o >>= 1) m = fmaxf(m, __shfl_xor_sync(0xffffffffu, m, o));
    if (lane == 0) red[warp] = m;
    __syncthreads();
    m = red[0];
#pragma unroll
    for (int j = 1; j < 8; j++) m = fmaxf(m, red[j]);
    __syncthreads();

    x.x = __expf(x.x - m); x.y = __expf(x.y - m);
    x.z = __expf(x.z - m); x.w = __expf(x.w - m);
    float s = x.x + x.y + x.z + x.w;
#pragma unroll
    for (int o = 16; o; o >>= 1) s += __shfl_xor_sync(0xffffffffu, s, o);
    if (lane == 0) red[warp] = s;
    __syncthreads();
    s = red[0];
#pragma unroll
    for (int j = 1; j < 8; j++) s += red[j];

    const float inv = 1.0f / s;
    __nv_bfloat16 h, l;
    __nv_bfloat162 h01, h23, l01, l23;
    split_bf16(x.x * inv, h, l); h01.x = h; l01.x = l;
    split_bf16(x.y * inv, h, l); h01.y = h; l01.y = l;
    split_bf16(x.z * inv, h, l); h23.x = h; l23.x = l;
    split_bf16(x.w * inv, h, l); h23.y = h; l23.y = l;
    ((__nv_bfloat162*)(Sh + row))[2 * tid]     = h01;
    ((__nv_bfloat162*)(Sh + row))[2 * tid + 1] = h23;
    ((__nv_bfloat162*)(Sl + row))[2 * tid]     = l01;
    ((__nv_bfloat162*)(Sl + row))[2 * tid + 1] = l23;
}

// ---------------------------------------------------------------------------
// Launch
// ---------------------------------------------------------------------------
extern "C" void kernel_launch(void* const* d_in, const int* in_sizes, int n_in,
                              void* d_out, int out_size)
{
    (void)in_sizes; (void)n_in; (void)out_size;

    const float* query = (const float*)d_in[0];
    const float* key   = (const float*)d_in[1];
    const float* value = (const float*)d_in[2];
    const float* w_q   = (const float*)d_in[3];
    const float* w_k   = (const float*)d_in[4];
    const float* w_v   = (const float*)d_in[5];
    const float* w_o   = (const float*)d_in[6];
    float*       out   = (float*)d_out;

    __nv_bfloat16 *qh, *ql, *kh, *kl, *vh, *vl;
    __nv_bfloat16 *wqTh, *wqTl, *wkTh, *wkTl, *wvTh, *wvTl, *worh, *worl;
    __nv_bfloat16 *Qh, *Ql, *Kh, *Kl, *Sh, *Sl, *Vth, *Vtl, *Ph, *Pl;
    float *Sf, *Of;
    cudaGetSymbolAddress((void**)&qh, g_qh);   cudaGetSymbolAddress((void**)&ql, g_ql);
    cudaGetSymbolAddress((void**)&kh, g_kh);   cudaGetSymbolAddress((void**)&kl, g_kl);
    cudaGetSymbolAddress((void**)&vh, g_vh);   cudaGetSymbolAddress((void**)&vl, g_vl);
    cudaGetSymbolAddress((void**)&wqTh, g_wqTh); cudaGetSymbolAddress((void**)&wqTl, g_wqTl);
    cudaGetSymbolAddress((void**)&wkTh, g_wkTh); cudaGetSymbolAddress((void**)&wkTl, g_wkTl);
    cudaGetSymbolAddress((void**)&wvTh, g_wvTh); cudaGetSymbolAddress((void**)&wvTl, g_wvTl);
    cudaGetSymbolAddress((void**)&worh, g_worh); cudaGetSymbolAddress((void**)&worl, g_worl);
    cudaGetSymbolAddress((void**)&Qh, g_Qh);   cudaGetSymbolAddress((void**)&Ql, g_Ql);
    cudaGetSymbolAddress((void**)&Kh, g_Kh);   cudaGetSymbolAddress((void**)&Kl, g_Kl);
    cudaGetSymbolAddress((void**)&Sf, g_Sf);
    cudaGetSymbolAddress((void**)&Sh, g_Sh);   cudaGetSymbolAddress((void**)&Sl, g_Sl);
    cudaGetSymbolAddress((void**)&Vth, g_Vth); cudaGetSymbolAddress((void**)&Vtl, g_Vtl);
    cudaGetSymbolAddress((void**)&Of, g_Of);
    cudaGetSymbolAddress((void**)&Ph, g_Ph);   cudaGetSymbolAddress((void**)&Pl, g_Pl);

    constexpr int SMEM_W  = 3 * 2 * (128 + 256) * 40 * 2;   // 184320
    constexpr int SMEM_64 = 4 * 2 * (128 + 64)  * 40 * 2;   // 122880
    cudaFuncSetAttribute(gemm_bf16x3_wide, cudaFuncAttributeMaxDynamicSharedMemorySize, SMEM_W);
    cudaFuncSetAttribute(gemm_bf16x3<64>,  cudaFuncAttributeMaxDynamicSharedMemorySize, SMEM_64);

    const long long MB = 1024LL * 1024LL;
    const int ZBH = B_ * H_;

    // ---- 0. split inputs into bf16 hi/lo
    split_copy_kernel<<<(B_ * N_ * DM_ / 4 + 255) / 256, 256>>>((const float4*)query, qh, ql, B_ * N_ * DM_ / 4);
    split_copy_kernel<<<(B_ * N_ * DM_ / 4 + 255) / 256, 256>>>((const float4*)key,   kh, kl, B_ * N_ * DM_ / 4);
    split_copy_kernel<<<(B_ * N_ * DM_ / 4 + 255) / 256, 256>>>((const float4*)value, vh, vl, B_ * N_ * DM_ / 4);
    split_copy_kernel<<<(DM_ * H_ * DV_ / 4 + 255) / 256, 256>>>((const float4*)w_o,  worh, worl, DM_ * H_ * DV_ / 4);

    // ---- 0b. transpose+split weights: [h][d][x] -> [h][x][d]
    transpose_split_kernel<<<dim3(DK_ / 32, DM_ / 32, H_), dim3(32, 8)>>>(
        w_q, wqTh, wqTl, DK_, DM_, (long long)DM_ * DK_, 0, (long long)DK_ * DM_, 0, 1);
    transpose_split_kernel<<<dim3(DK_ / 32, DM_ / 32, H_), dim3(32, 8)>>>(
        w_k, wkTh, wkTl, DK_, DM_, (long long)DM_ * DK_, 0, (long long)DK_ * DM_, 0, 1);
    transpose_split_kernel<<<dim3(DV_ / 32, DM_ / 32, H_), dim3(32, 8)>>>(
        w_v, wvTh, wvTl, DV_, DM_, (long long)DM_ * DV_, 0, (long long)DV_ * DM_, 0, 1);

    // ---- 1. Q projection : per (b,h)  M=1024 N=64 K=1024  -> split
    gemm_bf16x3<64><<<dim3(1, 8, ZBH), 256, SMEM_64>>>(
        qh, ql, wqTh, wqTl, nullptr, Qh, Ql,
        DM_, DM_, DM_, DK_,
        (long long)N_ * DM_, 0,
        0, (long long)DK_ * DM_,
        (long long)H_ * N_ * DK_, (long long)N_ * DK_,
        H_, 1.0f, 1);

    // ---- 2. K projection -> split
    gemm_bf16x3<64><<<dim3(1, 8, ZBH), 256, SMEM_64>>>(
        kh, kl, wkTh, wkTl, nullptr, Kh, Kl,
        DM_, DM_, DM_, DK_,
        (long long)N_ * DM_, 0,
        0, (long long)DK_ * DM_,
        (long long)H_ * N_ * DK_, (long long)N_ * DK_,
        H_, 1.0f, 1);

    // ---- 3. scores = (Q @ K^T)/8 : per z  M=1024 N=1024 K=64 -> fp32
    gemm_bf16x3_wide<<<dim3(4, 8, ZBH), 256, SMEM_W>>>(
        Qh, Ql, Kh, Kl, Sf, nullptr, nullptr,
        DK_, DK_, DK_, N_,
        (long long)N_ * DK_, 0,
        (long long)N_ * DK_, 0,
        (long long)N_ * N_, 0,
        1, 0.125f, 0);

    // ---- 4. softmax rows -> split S
    softmax_split_kernel<<<ZBH * N_, 256>>>(Sf, Sh, Sl);

    // ---- 5. Vt[v,m] = sum_d wvT[h][v,d] * v[b][m,d] : M=N=K=1024 -> split
    gemm_bf16x3_wide<<<dim3(4, 8, ZBH), 256, SMEM_W>>>(
        wvTh, wvTl, vh, vl, nullptr, Vth, Vtl,
        DM_, DM_, DM_, N_,
        0, (long long)DV_ * DM_,
        (long long)N_ * DM_, 0,
        (long long)H_ * DV_ * N_, (long long)DV_ * N_,
        H_, 1.0f, 1);

    // ---- 6. O[q,v] = sum_m S[q,m] * Vt[v,m] : M=N=K=1024 -> fp32
    gemm_bf16x3_wide<<<dim3(4, 8, ZBH), 256, SMEM_W>>>(
        Sh, Sl, Vth, Vtl, Of, nullptr, nullptr,
        N_, N_, N_, DV_,
        (long long)N_ * N_, 0,
        (long long)DV_ * N_, 0,
        (long long)N_ * DV_, 0,
        1, 1.0f, 0);

    // ---- 7. permute O[b,h,q,v] -> P[b][v][h*N+q], split
    transpose_split_kernel<<<dim3(32, 32, ZBH), dim3(32, 8)>>>(
        Of, Ph, Pl, DV_, H_ * N_,
        (long long)H_ * MB, MB,
        (long long)H_ * MB, (long long)N_,
        H_);

    // ---- 8. out[b][d,v] = sum_e wor[d,e] * P[b][v,e] : M=N=1024 K=16384
    gemm_bf16x3_wide<<<dim3(4, 8, B_), 256, SMEM_W>>>(
        worh, worl, Ph, Pl, out, nullptr, nullptr,
        H_ * N_, H_ * N_, H_ * N_, DV_,
        0, 0,
        (long long)DV_ * H_ * N_, 0,
        (long long)DM_ * DV_, 0,
        1, 1.0f, 0);
}

// round 6
// speedup vs baseline: 2.3759x; 1.0063x over previous
#include <cuda_runtime.h>
#include <cuda_bf16.h>
#include <cstdint>

// ---------------------------------------------------------------------------
// Problem constants
// ---------------------------------------------------------------------------
#define B_   4
#define N_   1024
#define DM_  1024
#define H_   16
#define DK_  64
#define DV_  1024

// ---------------------------------------------------------------------------
// Scratch (device globals; no allocations allowed). hi/lo bf16 split pairs.
// ---------------------------------------------------------------------------
__device__ __nv_bfloat16 g_qh [B_ * N_ * DM_],  g_ql [B_ * N_ * DM_];
__device__ __nv_bfloat16 g_kh [B_ * N_ * DM_],  g_kl [B_ * N_ * DM_];
__device__ __nv_bfloat16 g_vh [B_ * N_ * DM_],  g_vl [B_ * N_ * DM_];
__device__ __nv_bfloat16 g_wqTh[H_ * DK_ * DM_], g_wqTl[H_ * DK_ * DM_];
__device__ __nv_bfloat16 g_wkTh[H_ * DK_ * DM_], g_wkTl[H_ * DK_ * DM_];
__device__ __nv_bfloat16 g_wvTh[H_ * DV_ * DM_], g_wvTl[H_ * DV_ * DM_];
__device__ __nv_bfloat16 g_worh[DM_ * H_ * DV_], g_worl[DM_ * H_ * DV_];
__device__ __nv_bfloat16 g_Qh [B_ * H_ * N_ * DK_], g_Ql [B_ * H_ * N_ * DK_];
__device__ __nv_bfloat16 g_Kh [B_ * H_ * N_ * DK_], g_Kl [B_ * H_ * N_ * DK_];
__device__ float         g_Sf [B_ * H_ * N_ * N_];
__device__ __nv_bfloat16 g_Sh [B_ * H_ * N_ * N_],  g_Sl [B_ * H_ * N_ * N_];
__device__ __nv_bfloat16 g_Vth[B_ * H_ * DV_ * N_], g_Vtl[B_ * H_ * DV_ * N_];
__device__ float         g_Of [B_ * H_ * N_ * DV_];
__device__ __nv_bfloat16 g_Ph [B_ * DV_ * H_ * N_], g_Pl [B_ * DV_ * H_ * N_];

// ---------------------------------------------------------------------------
// helpers
// ---------------------------------------------------------------------------
__device__ __forceinline__ uint32_t smem_u32(const void* p) {
    uint32_t a;
    asm("{ .reg .u64 t; cvta.to.shared.u64 t, %1; cvt.u32.u64 %0, t; }"
        : "=r"(a) : "l"(p));
    return a;
}

__device__ __forceinline__ void split_bf16(float x, __nv_bfloat16& h, __nv_bfloat16& l) {
    h = __float2bfloat16_rn(x);
    l = __float2bfloat16_rn(x - __bfloat162float(h));
}

__device__ __forceinline__ void cp_async16(uint32_t saddr, const void* gptr) {
    asm volatile("cp.async.cg.shared.global [%0], [%1], 16;"
                 :: "r"(saddr), "l"(gptr));
}

__device__ __forceinline__ uint32_t lds_u32(const __nv_bfloat16* p) {
    return *reinterpret_cast<const uint32_t*>(p);
}

__device__ __forceinline__ void mma_bf16(float* c,
                                         uint32_t a0, uint32_t a1, uint32_t a2, uint32_t a3,
                                         uint32_t b0, uint32_t b1)
{
    asm volatile(
        "mma.sync.aligned.m16n8k16.row.col.f32.bf16.bf16.f32 "
        "{%0,%1,%2,%3}, {%4,%5,%6,%7}, {%8,%9}, {%0,%1,%2,%3};"
        : "+f"(c[0]), "+f"(c[1]), "+f"(c[2]), "+f"(c[3])
        : "r"(a0), "r"(a1), "r"(a2), "r"(a3), "r"(b0), "r"(b1));
}

#define LDSM4(r, addr) \
    asm volatile("ldmatrix.sync.aligned.m8n8.x4.shared.b16 {%0,%1,%2,%3}, [%4];" \
        : "=r"((r)[0]), "=r"((r)[1]), "=r"((r)[2]), "=r"((r)[3]) : "r"(addr))

// ===========================================================================
// WIDE 3xBF16 GEMM: CTA tile 128 x 256, 512 threads (warp grid 4x4, warp
// tile 32 x 64), ldmatrix fragment loads, 3-stage cp.async pipeline.
//   C[m,n] = alpha * sum_k (Ah+Al)[m,k]*(Bh+Bl)[n,k]   (Al*Bl dropped)
// mode 0: fp32 C.   mode 1: split Ch/Cl bf16.
// ===========================================================================
__global__ void __launch_bounds__(512, 1)
gemm_bf16x3_wide(const __nv_bfloat16* __restrict__ Ah, const __nv_bfloat16* __restrict__ Al,
                 const __nv_bfloat16* __restrict__ Bh, const __nv_bfloat16* __restrict__ Bl,
                 float* __restrict__ C,
                 __nv_bfloat16* __restrict__ Ch, __nv_bfloat16* __restrict__ Cl,
                 int Kdim, int lda, int ldb, int ldc,
                 long long sAo, long long sAi,
                 long long sBo, long long sBi,
                 long long sCo, long long sCi,
                 int inner, float alpha, int mode)
{
    constexpr int BM = 128, BN = 256, BK = 32, STAGES = 3, THREADS = 512;
    constexpr int LDB = 40;                         // bf16 units; 80 B row stride
    constexpr int AL_OFF = BM * LDB;
    constexpr int BH_OFF = 2 * BM * LDB;
    constexpr int STG    = 2 * (BM + BN) * LDB;     // 30720 bf16 = 61440 B
    constexpr int MT = 2;                           // 32/16 m16 tiles per warp
    constexpr int NPAIR = 4;                        // 64/16 n16 pairs per warp
    constexpr int A_IT = BM * 4 / THREADS;          // 1 chunk/thread/array
    constexpr int B_IT = BN * 4 / THREADS;          // 2

    extern __shared__ __nv_bfloat16 sm[];

    const int tid  = threadIdx.x;
    const int wid  = tid >> 5;
    const int lane = tid & 31;
    const int g    = lane >> 2;
    const int t    = lane & 3;

    const int z  = blockIdx.z;
    const int zo = z / inner;
    const int zi = z - zo * inner;
    Ah += zo * sAo + zi * sAi;  Al += zo * sAo + zi * sAi;
    Bh += zo * sBo + zi * sBi;  Bl += zo * sBo + zi * sBi;
    const long long coff = zo * sCo + zi * sCi;
    const int m0 = blockIdx.y * BM;
    const int n0 = blockIdx.x * BN;

    const int wm0 = (wid & 3) * 32;     // warp grid 4 (m) x 4 (n)
    const int wn0 = (wid >> 2) * 64;

    const uint32_t sbase = smem_u32(sm);

    // ldmatrix per-lane byte offsets
    const int q = lane >> 3;
    const uint32_t a_lane = (uint32_t)(((q & 1) * 8 + (lane & 7)) * LDB * 2 + (q >> 1) * 16);
    const uint32_t b_lane = (uint32_t)(((q >> 1) * 8 + (lane & 7)) * LDB * 2 + (q & 1) * 16);

    // cp.async mapping: chunk c -> row c>>2, 8-bf16 col (c&3)*8
    int  a_go[A_IT]; uint32_t a_sp[A_IT];
#pragma unroll
    for (int i = 0; i < A_IT; i++) {
        int c = tid + i * THREADS;
        int row = c >> 2, kc = (c & 3) * 8;
        a_go[i] = (m0 + row) * lda + kc;
        a_sp[i] = (uint32_t)(row * LDB + kc) * 2u;
    }
    int  b_go[B_IT]; uint32_t b_sp[B_IT];
#pragma unroll
    for (int i = 0; i < B_IT; i++) {
        int c = tid + i * THREADS;
        int row = c >> 2, kc = (c & 3) * 8;
        b_go[i] = (n0 + row) * ldb + kc;
        b_sp[i] = (uint32_t)(row * LDB + kc) * 2u;
    }

    const int T = Kdim / BK;

    float acc[MT][8][4];
#pragma unroll
    for (int i = 0; i < MT; i++)
#pragma unroll
        for (int j = 0; j < 8; j++)
#pragma unroll
            for (int r = 0; r < 4; r++) acc[i][j][r] = 0.f;

    // ---- prologue ----
#pragma unroll
    for (int p = 0; p < STAGES - 1; p++) {
        if (p < T) {
            uint32_t sb = sbase + (uint32_t)((p % STAGES) * STG) * 2u;
#pragma unroll
            for (int i = 0; i < A_IT; i++) {
                cp_async16(sb + a_sp[i], Ah + a_go[i] + p * BK);
                cp_async16(sb + AL_OFF * 2 + a_sp[i], Al + a_go[i] + p * BK);
            }
#pragma unroll
            for (int i = 0; i < B_IT; i++) {
                cp_async16(sb + BH_OFF * 2 + b_sp[i], Bh + b_go[i] + p * BK);
                cp_async16(sb + (BH_OFF + BN * LDB) * 2 + b_sp[i], Bl + b_go[i] + p * BK);
            }
        }
        asm volatile("cp.async.commit_group;" ::: "memory");
    }

    for (int kt = 0; kt < T; kt++) {
        asm volatile("cp.async.wait_group %0;" :: "n"(STAGES - 2) : "memory");
        __syncthreads();

        {   // prefetch tile kt+STAGES-1
            int tl = kt + STAGES - 1;
            if (tl < T) {
                uint32_t sb = sbase + (uint32_t)((tl % STAGES) * STG) * 2u;
#pragma unroll
                for (int i = 0; i < A_IT; i++) {
                    cp_async16(sb + a_sp[i], Ah + a_go[i] + tl * BK);
                    cp_async16(sb + AL_OFF * 2 + a_sp[i], Al + a_go[i] + tl * BK);
                }
#pragma unroll
                for (int i = 0; i < B_IT; i++) {
                    cp_async16(sb + BH_OFF * 2 + b_sp[i], Bh + b_go[i] + tl * BK);
                    cp_async16(sb + (BH_OFF + BN * LDB) * 2 + b_sp[i], Bl + b_go[i] + tl * BK);
                }
            }
            asm volatile("cp.async.commit_group;" ::: "memory");
        }

        const uint32_t stg = sbase + (uint32_t)((kt % STAGES) * STG) * 2u;
#pragma unroll
        for (int kk = 0; kk < BK; kk += 16) {
            uint32_t ah[MT][4], al[MT][4];
#pragma unroll
            for (int mt = 0; mt < MT; mt++) {
                uint32_t aa = stg + a_lane + (uint32_t)((wm0 + mt * 16) * LDB + kk) * 2u;
                LDSM4(ah[mt], aa);
                LDSM4(al[mt], aa + (uint32_t)(AL_OFF * 2));
            }
#pragma unroll
            for (int pr = 0; pr < NPAIR; pr++) {
                uint32_t bh4[4], bl4[4];
                uint32_t ba = stg + (uint32_t)(BH_OFF * 2) + b_lane
                            + (uint32_t)((wn0 + pr * 16) * LDB + kk) * 2u;
                LDSM4(bh4, ba);
                LDSM4(bl4, ba + (uint32_t)(BN * LDB * 2));
                const int nt0 = pr * 2, nt1 = pr * 2 + 1;
#pragma unroll
                for (int mt = 0; mt < MT; mt++) {
                    mma_bf16(acc[mt][nt0], ah[mt][0], ah[mt][1], ah[mt][2], ah[mt][3], bh4[0], bh4[1]);
                    mma_bf16(acc[mt][nt0], ah[mt][0], ah[mt][1], ah[mt][2], ah[mt][3], bl4[0], bl4[1]);
                    mma_bf16(acc[mt][nt0], al[mt][0], al[mt][1], al[mt][2], al[mt][3], bh4[0], bh4[1]);
                    mma_bf16(acc[mt][nt1], ah[mt][0], ah[mt][1], ah[mt][2], ah[mt][3], bh4[2], bh4[3]);
                    mma_bf16(acc[mt][nt1], ah[mt][0], ah[mt][1], ah[mt][2], ah[mt][3], bl4[2], bl4[3]);
                    mma_bf16(acc[mt][nt1], al[mt][0], al[mt][1], al[mt][2], al[mt][3], bh4[2], bh4[3]);
                }
            }
        }
    }

    // ---- epilogue ----
#pragma unroll
    for (int mt = 0; mt < MT; mt++) {
        const int r0 = m0 + wm0 + mt * 16 + g;
#pragma unroll
        for (int nt = 0; nt < 8; nt++) {
            const int cc = n0 + wn0 + nt * 8 + 2 * t;
            float v00 = acc[mt][nt][0] * alpha, v01 = acc[mt][nt][1] * alpha;
            float v10 = acc[mt][nt][2] * alpha, v11 = acc[mt][nt][3] * alpha;
            if (mode == 0) {
                float2 u0; u0.x = v00; u0.y = v01;
                float2 u1; u1.x = v10; u1.y = v11;
                *(float2*)&C[coff + (long long)r0 * ldc + cc]       = u0;
                *(float2*)&C[coff + (long long)(r0 + 8) * ldc + cc] = u1;
            } else {
                __nv_bfloat16 h0, l0, h1, l1;
                split_bf16(v00, h0, l0); split_bf16(v01, h1, l1);
                __nv_bfloat162 hh; hh.x = h0; hh.y = h1;
                __nv_bfloat162 ll; ll.x = l0; ll.y = l1;
                *(__nv_bfloat162*)&Ch[coff + (long long)r0 * ldc + cc] = hh;
                *(__nv_bfloat162*)&Cl[coff + (long long)r0 * ldc + cc] = ll;
                split_bf16(v10, h0, l0); split_bf16(v11, h1, l1);
                hh.x = h0; hh.y = h1; ll.x = l0; ll.y = l1;
                *(__nv_bfloat162*)&Ch[coff + (long long)(r0 + 8) * ldc + cc] = hh;
                *(__nv_bfloat162*)&Cl[coff + (long long)(r0 + 8) * ldc + cc] = ll;
            }
        }
    }
}

// ===========================================================================
// Narrow 3xBF16 GEMM (BN=64) — proven R4 kernel, used for Q/K projections.
// ===========================================================================
template<int BN>
__global__ void __launch_bounds__(256)
gemm_bf16x3(const __nv_bfloat16* __restrict__ Ah, const __nv_bfloat16* __restrict__ Al,
            const __nv_bfloat16* __restrict__ Bh, const __nv_bfloat16* __restrict__ Bl,
            float* __restrict__ C,
            __nv_bfloat16* __restrict__ Ch, __nv_bfloat16* __restrict__ Cl,
            int Kdim, int lda, int ldb, int ldc,
            long long sAo, long long sAi,
            long long sBo, long long sBi,
            long long sCo, long long sCi,
            int inner, float alpha, int mode)
{
    constexpr int BM = 128, BK = 32, STAGES = 4;
    constexpr int LDB = 40;
    constexpr int AL_OFF = BM * LDB;
    constexpr int BH_OFF = 2 * BM * LDB;
    constexpr int STG    = 2 * (BM + BN) * LDB;
    constexpr int WM = 4, WN = 2;
    constexpr int MT = (BM / WM) / 16;
    constexpr int NT = (BN / WN) / 8;
    constexpr int A_IT = BM * 4 / 256;
    constexpr int B_IT = BN * 4 / 256;

    extern __shared__ __nv_bfloat16 sm[];

    const int tid  = threadIdx.x;
    const int wid  = tid >> 5;
    const int lane = tid & 31;
    const int g    = lane >> 2;
    const int t    = lane & 3;

    const int z  = blockIdx.z;
    const int zo = z / inner;
    const int zi = z - zo * inner;
    Ah += zo * sAo + zi * sAi;  Al += zo * sAo + zi * sAi;
    Bh += zo * sBo + zi * sBi;  Bl += zo * sBo + zi * sBi;
    const long long coff = zo * sCo + zi * sCi;
    const int m0 = blockIdx.y * BM;
    const int n0 = blockIdx.x * BN;

    const int wm0 = (wid % WM) * (BM / WM);
    const int wn0 = (wid / WM) * (BN / WN);

    const uint32_t sbase = smem_u32(sm);

    int  a_go[A_IT]; uint32_t a_sp[A_IT];
#pragma unroll
    for (int i = 0; i < A_IT; i++) {
        int c = tid + i * 256;
        int row = c >> 2, kc = (c & 3) * 8;
        a_go[i] = (m0 + row) * lda + kc;
        a_sp[i] = (uint32_t)(row * LDB + kc) * 2u;
    }
    int  b_go[B_IT]; uint32_t b_sp[B_IT];
#pragma unroll
    for (int i = 0; i < B_IT; i++) {
        int c = tid + i * 256;
        int row = c >> 2, kc = (c & 3) * 8;
        b_go[i] = (n0 + row) * ldb + kc;
        b_sp[i] = (uint32_t)(row * LDB + kc) * 2u;
    }

    const int T = Kdim / BK;

    float acc[MT][NT][4];
#pragma unroll
    for (int i = 0; i < MT; i++)
#pragma unroll
        for (int j = 0; j < NT; j++)
#pragma unroll
            for (int r = 0; r < 4; r++) acc[i][j][r] = 0.f;

#pragma unroll
    for (int p = 0; p < STAGES - 1; p++) {
        if (p < T) {
            uint32_t sb = sbase + (uint32_t)((p % STAGES) * STG) * 2u;
#pragma unroll
            for (int i = 0; i < A_IT; i++) {
                cp_async16(sb + a_sp[i], Ah + a_go[i] + p * BK);
                cp_async16(sb + AL_OFF * 2 + a_sp[i], Al + a_go[i] + p * BK);
            }
#pragma unroll
            for (int i = 0; i < B_IT; i++) {
                cp_async16(sb + BH_OFF * 2 + b_sp[i], Bh + b_go[i] + p * BK);
                cp_async16(sb + (BH_OFF + BN * LDB) * 2 + b_sp[i], Bl + b_go[i] + p * BK);
            }
        }
        asm volatile("cp.async.commit_group;" ::: "memory");
    }

    for (int kt = 0; kt < T; kt++) {
        asm volatile("cp.async.wait_group %0;" :: "n"(STAGES - 2) : "memory");
        __syncthreads();

        {
            int tl = kt + STAGES - 1;
            if (tl < T) {
                uint32_t sb = sbase + (uint32_t)((tl % STAGES) * STG) * 2u;
#pragma unroll
                for (int i = 0; i < A_IT; i++) {
                    cp_async16(sb + a_sp[i], Ah + a_go[i] + tl * BK);
                    cp_async16(sb + AL_OFF * 2 + a_sp[i], Al + a_go[i] + tl * BK);
                }
#pragma unroll
                for (int i = 0; i < B_IT; i++) {
                    cp_async16(sb + BH_OFF * 2 + b_sp[i], Bh + b_go[i] + tl * BK);
                    cp_async16(sb + (BH_OFF + BN * LDB) * 2 + b_sp[i], Bl + b_go[i] + tl * BK);
                }
            }
            asm volatile("cp.async.commit_group;" ::: "memory");
        }

        const __nv_bfloat16* st = sm + (kt % STAGES) * STG;
        const __nv_bfloat16* sB = st + BH_OFF;
#pragma unroll
        for (int kk = 0; kk < BK; kk += 16) {
            uint32_t bh[NT][2], bl[NT][2];
#pragma unroll
            for (int nt = 0; nt < NT; nt++) {
                const __nv_bfloat16* bp = sB + (wn0 + nt * 8 + g) * LDB + kk + 2 * t;
                bh[nt][0] = lds_u32(bp);
                bh[nt][1] = lds_u32(bp + 8);
                bl[nt][0] = lds_u32(bp + BN * LDB);
                bl[nt][1] = lds_u32(bp + BN * LDB + 8);
            }
#pragma unroll
            for (int mt = 0; mt < MT; mt++) {
                const __nv_bfloat16* ap = st + (wm0 + mt * 16 + g) * LDB + kk + 2 * t;
                uint32_t ah0 = lds_u32(ap);
                uint32_t ah1 = lds_u32(ap + 8 * LDB);
                uint32_t ah2 = lds_u32(ap + 8);
                uint32_t ah3 = lds_u32(ap + 8 * LDB + 8);
                const __nv_bfloat16* alp = ap + AL_OFF;
                uint32_t al0 = lds_u32(alp);
                uint32_t al1 = lds_u32(alp + 8 * LDB);
                uint32_t al2 = lds_u32(alp + 8);
                uint32_t al3 = lds_u32(alp + 8 * LDB + 8);
#pragma unroll
                for (int nt = 0; nt < NT; nt++) {
                    mma_bf16(acc[mt][nt], ah0, ah1, ah2, ah3, bh[nt][0], bh[nt][1]);
                    mma_bf16(acc[mt][nt], ah0, ah1, ah2, ah3, bl[nt][0], bl[nt][1]);
                    mma_bf16(acc[mt][nt], al0, al1, al2, al3, bh[nt][0], bh[nt][1]);
                }
            }
        }
    }

#pragma unroll
    for (int mt = 0; mt < MT; mt++) {
        const int r0 = m0 + wm0 + mt * 16 + g;
#pragma unroll
        for (int nt = 0; nt < NT; nt++) {
            const int cc = n0 + wn0 + nt * 8 + 2 * t;
            float v00 = acc[mt][nt][0] * alpha, v01 = acc[mt][nt][1] * alpha;
            float v10 = acc[mt][nt][2] * alpha, v11 = acc[mt][nt][3] * alpha;
            if (mode == 0) {
                float2 u0; u0.x = v00; u0.y = v01;
                float2 u1; u1.x = v10; u1.y = v11;
                *(float2*)&C[coff + (long long)r0 * ldc + cc]       = u0;
                *(float2*)&C[coff + (long long)(r0 + 8) * ldc + cc] = u1;
            } else {
                __nv_bfloat16 h0, l0, h1, l1;
                split_bf16(v00, h0, l0); split_bf16(v01, h1, l1);
                __nv_bfloat162 hh; hh.x = h0; hh.y = h1;
                __nv_bfloat162 ll; ll.x = l0; ll.y = l1;
                *(__nv_bfloat162*)&Ch[coff + (long long)r0 * ldc + cc] = hh;
                *(__nv_bfloat162*)&Cl[coff + (long long)r0 * ldc + cc] = ll;
                split_bf16(v10, h0, l0); split_bf16(v11, h1, l1);
                hh.x = h0; hh.y = h1; ll.x = l0; ll.y = l1;
                *(__nv_bfloat162*)&Ch[coff + (long long)(r0 + 8) * ldc + cc] = hh;
                *(__nv_bfloat162*)&Cl[coff + (long long)(r0 + 8) * ldc + cc] = ll;
            }
        }
    }
}

// ---------------------------------------------------------------------------
// fp32 -> (hi, lo) bf16 split copy
// ---------------------------------------------------------------------------
__global__ void split_copy_kernel(const float4* __restrict__ in,
                                  __nv_bfloat16* __restrict__ oh,
                                  __nv_bfloat16* __restrict__ ol, int n4)
{
    int i = blockIdx.x * blockDim.x + threadIdx.x;
    if (i < n4) {
        float4 v = in[i];
        __nv_bfloat16 h, l;
        __nv_bfloat162 h01, h23, l01, l23;
        split_bf16(v.x, h, l); h01.x = h; l01.x = l;
        split_bf16(v.y, h, l); h01.y = h; l01.y = l;
        split_bf16(v.z, h, l); h23.x = h; l23.x = l;
        split_bf16(v.w, h, l); h23.y = h; l23.y = l;
        ((__nv_bfloat162*)oh)[2 * i] = h01; ((__nv_bfloat162*)oh)[2 * i + 1] = h23;
        ((__nv_bfloat162*)ol)[2 * i] = l01; ((__nv_bfloat162*)ol)[2 * i + 1] = l23;
    }
}

// ---------------------------------------------------------------------------
// Batched 32x32 transpose with bf16 hi/lo split output.
// ---------------------------------------------------------------------------
__global__ void transpose_split_kernel(const float* __restrict__ in,
                                       __nv_bfloat16* __restrict__ oh,
                                       __nv_bfloat16* __restrict__ ol,
                                       int ldi, int ldo,
                                       long long sIo, long long sIi,
                                       long long sOo, long long sOi, int inner)
{
    __shared__ float tile[32][33];
    const int z  = blockIdx.z;
    const int zo = z / inner, zi = z - zo * inner;
    const float* ip = in + zo * sIo + zi * sIi;
    const long long oo = zo * sOo + zi * sOi;
    const int c0 = blockIdx.x * 32, r0 = blockIdx.y * 32;
    const int tx = threadIdx.x, ty = threadIdx.y;
#pragma unroll
    for (int i = 0; i < 32; i += 8)
        tile[ty + i][tx] = ip[(long long)(r0 + ty + i) * ldi + c0 + tx];
    __syncthreads();
#pragma unroll
    for (int i = 0; i < 32; i += 8) {
        float v = tile[tx][ty + i];
        __nv_bfloat16 h, l;
        split_bf16(v, h, l);
        long long o = oo + (long long)(c0 + ty + i) * ldo + r0 + tx;
        oh[o] = h; ol[o] = l;
    }
}

// ---------------------------------------------------------------------------
// Row softmax: fp32 in, bf16 hi/lo out. One block per 1024-wide row.
// ---------------------------------------------------------------------------
__global__ void softmax_split_kernel(const float* __restrict__ Sf,
                                     __nv_bfloat16* __restrict__ Sh,
                                     __nv_bfloat16* __restrict__ Sl)
{
    __shared__ float red[8];
    const long long row = (long long)blockIdx.x * N_;
    const float4* p = (const float4*)(Sf + row);
    const int tid  = threadIdx.x;
    const int lane = tid & 31;
    const int warp = tid >> 5;

    float4 x = p[tid];

    float m = fmaxf(fmaxf(x.x, x.y), fmaxf(x.z, x.w));
#pragma unroll
    for (int o = 16; o; o >>= 1) m = fmaxf(m, __shfl_xor_sync(0xffffffffu, m, o));
    if (lane == 0) red[warp] = m;
    __syncthreads();
    m = red[0];
#pragma unroll
    for (int j = 1; j < 8; j++) m = fmaxf(m, red[j]);
    __syncthreads();

    x.x = __expf(x.x - m); x.y = __expf(x.y - m);
    x.z = __expf(x.z - m); x.w = __expf(x.w - m);
    float s = x.x + x.y + x.z + x.w;
#pragma unroll
    for (int o = 16; o; o >>= 1) s += __shfl_xor_sync(0xffffffffu, s, o);
    if (lane == 0) red[warp] = s;
    __syncthreads();
    s = red[0];
#pragma unroll
    for (int j = 1; j < 8; j++) s += red[j];

    const float inv = 1.0f / s;
    __nv_bfloat16 h, l;
    __nv_bfloat162 h01, h23, l01, l23;
    split_bf16(x.x * inv, h, l); h01.x = h; l01.x = l;
    split_bf16(x.y * inv, h, l); h01.y = h; l01.y = l;
    split_bf16(x.z * inv, h, l); h23.x = h; l23.x = l;
    split_bf16(x.w * inv, h, l); h23.y = h; l23.y = l;
    ((__nv_bfloat162*)(Sh + row))[2 * tid]     = h01;
    ((__nv_bfloat162*)(Sh + row))[2 * tid + 1] = h23;
    ((__nv_bfloat162*)(Sl + row))[2 * tid]     = l01;
    ((__nv_bfloat162*)(Sl + row))[2 * tid + 1] = l23;
}

// ---------------------------------------------------------------------------
// Launch
// ---------------------------------------------------------------------------
extern "C" void kernel_launch(void* const* d_in, const int* in_sizes, int n_in,
                              void* d_out, int out_size)
{
    (void)in_sizes; (void)n_in; (void)out_size;

    const float* query = (const float*)d_in[0];
    const float* key   = (const float*)d_in[1];
    const float* value = (const float*)d_in[2];
    const float* w_q   = (const float*)d_in[3];
    const float* w_k   = (const float*)d_in[4];
    const float* w_v   = (const float*)d_in[5];
    const float* w_o   = (const float*)d_in[6];
    float*       out   = (float*)d_out;

    __nv_bfloat16 *qh, *ql, *kh, *kl, *vh, *vl;
    __nv_bfloat16 *wqTh, *wqTl, *wkTh, *wkTl, *wvTh, *wvTl, *worh, *worl;
    __nv_bfloat16 *Qh, *Ql, *Kh, *Kl, *Sh, *Sl, *Vth, *Vtl, *Ph, *Pl;
    float *Sf, *Of;
    cudaGetSymbolAddress((void**)&qh, g_qh);   cudaGetSymbolAddress((void**)&ql, g_ql);
    cudaGetSymbolAddress((void**)&kh, g_kh);   cudaGetSymbolAddress((void**)&kl, g_kl);
    cudaGetSymbolAddress((void**)&vh, g_vh);   cudaGetSymbolAddress((void**)&vl, g_vl);
    cudaGetSymbolAddress((void**)&wqTh, g_wqTh); cudaGetSymbolAddress((void**)&wqTl, g_wqTl);
    cudaGetSymbolAddress((void**)&wkTh, g_wkTh); cudaGetSymbolAddress((void**)&wkTl, g_wkTl);
    cudaGetSymbolAddress((void**)&wvTh, g_wvTh); cudaGetSymbolAddress((void**)&wvTl, g_wvTl);
    cudaGetSymbolAddress((void**)&worh, g_worh); cudaGetSymbolAddress((void**)&worl, g_worl);
    cudaGetSymbolAddress((void**)&Qh, g_Qh);   cudaGetSymbolAddress((void**)&Ql, g_Ql);
    cudaGetSymbolAddress((void**)&Kh, g_Kh);   cudaGetSymbolAddress((void**)&Kl, g_Kl);
    cudaGetSymbolAddress((void**)&Sf, g_Sf);
    cudaGetSymbolAddress((void**)&Sh, g_Sh);   cudaGetSymbolAddress((void**)&Sl, g_Sl);
    cudaGetSymbolAddress((void**)&Vth, g_Vth); cudaGetSymbolAddress((void**)&Vtl, g_Vtl);
    cudaGetSymbolAddress((void**)&Of, g_Of);
    cudaGetSymbolAddress((void**)&Ph, g_Ph);   cudaGetSymbolAddress((void**)&Pl, g_Pl);

    constexpr int SMEM_W  = 3 * 2 * (128 + 256) * 40 * 2;   // 184320
    constexpr int SMEM_64 = 4 * 2 * (128 + 64)  * 40 * 2;   // 122880
    cudaFuncSetAttribute(gemm_bf16x3_wide, cudaFuncAttributeMaxDynamicSharedMemorySize, SMEM_W);
    cudaFuncSetAttribute(gemm_bf16x3<64>,  cudaFuncAttributeMaxDynamicSharedMemorySize, SMEM_64);

    const long long MB = 1024LL * 1024LL;
    const int ZBH = B_ * H_;

    // ---- 0. split inputs into bf16 hi/lo
    split_copy_kernel<<<(B_ * N_ * DM_ / 4 + 255) / 256, 256>>>((const float4*)query, qh, ql, B_ * N_ * DM_ / 4);
    split_copy_kernel<<<(B_ * N_ * DM_ / 4 + 255) / 256, 256>>>((const float4*)key,   kh, kl, B_ * N_ * DM_ / 4);
    split_copy_kernel<<<(B_ * N_ * DM_ / 4 + 255) / 256, 256>>>((const float4*)value, vh, vl, B_ * N_ * DM_ / 4);
    split_copy_kernel<<<(DM_ * H_ * DV_ / 4 + 255) / 256, 256>>>((const float4*)w_o,  worh, worl, DM_ * H_ * DV_ / 4);

    // ---- 0b. transpose+split weights: [h][d][x] -> [h][x][d]
    transpose_split_kernel<<<dim3(DK_ / 32, DM_ / 32, H_), dim3(32, 8)>>>(
        w_q, wqTh, wqTl, DK_, DM_, (long long)DM_ * DK_, 0, (long long)DK_ * DM_, 0, 1);
    transpose_split_kernel<<<dim3(DK_ / 32, DM_ / 32, H_), dim3(32, 8)>>>(
        w_k, wkTh, wkTl, DK_, DM_, (long long)DM_ * DK_, 0, (long long)DK_ * DM_, 0, 1);
    transpose_split_kernel<<<dim3(DV_ / 32, DM_ / 32, H_), dim3(32, 8)>>>(
        w_v, wvTh, wvTl, DV_, DM_, (long long)DM_ * DV_, 0, (long long)DV_ * DM_, 0, 1);

    // ---- 1. Q projection : per (b,h)  M=1024 N=64 K=1024  -> split
    gemm_bf16x3<64><<<dim3(1, 8, ZBH), 256, SMEM_64>>>(
        qh, ql, wqTh, wqTl, nullptr, Qh, Ql,
        DM_, DM_, DM_, DK_,
        (long long)N_ * DM_, 0,
        0, (long long)DK_ * DM_,
        (long long)H_ * N_ * DK_, (long long)N_ * DK_,
        H_, 1.0f, 1);

    // ---- 2. K projection -> split
    gemm_bf16x3<64><<<dim3(1, 8, ZBH), 256, SMEM_64>>>(
        kh, kl, wkTh, wkTl, nullptr, Kh, Kl,
        DM_, DM_, DM_, DK_,
        (long long)N_ * DM_, 0,
        0, (long long)DK_ * DM_,
        (long long)H_ * N_ * DK_, (long long)N_ * DK_,
        H_, 1.0f, 1);

    // ---- 3. scores = (Q @ K^T)/8 : per z  M=1024 N=1024 K=64 -> fp32
    gemm_bf16x3_wide<<<dim3(4, 8, ZBH), 512, SMEM_W>>>(
        Qh, Ql, Kh, Kl, Sf, nullptr, nullptr,
        DK_, DK_, DK_, N_,
        (long long)N_ * DK_, 0,
        (long long)N_ * DK_, 0,
        (long long)N_ * N_, 0,
        1, 0.125f, 0);

    // ---- 4. softmax rows -> split S
    softmax_split_kernel<<<ZBH * N_, 256>>>(Sf, Sh, Sl);

    // ---- 5. Vt[v,m] = sum_d wvT[h][v,d] * v[b][m,d] : M=N=K=1024 -> split
    gemm_bf16x3_wide<<<dim3(4, 8, ZBH), 512, SMEM_W>>>(
        wvTh, wvTl, vh, vl, nullptr, Vth, Vtl,
        DM_, DM_, DM_, N_,
        0, (long long)DV_ * DM_,
        (long long)N_ * DM_, 0,
        (long long)H_ * DV_ * N_, (long long)DV_ * N_,
        H_, 1.0f, 1);

    // ---- 6. O[q,v] = sum_m S[q,m] * Vt[v,m] : M=N=K=1024 -> fp32
    gemm_bf16x3_wide<<<dim3(4, 8, ZBH), 512, SMEM_W>>>(
        Sh, Sl, Vth, Vtl, Of, nullptr, nullptr,
        N_, N_, N_, DV_,
        (long long)N_ * N_, 0,
        (long long)DV_ * N_, 0,
        (long long)N_ * DV_, 0,
        1, 1.0f, 0);

    // ---- 7. permute O[b,h,q,v] -> P[b][v][h*N+q], split
    transpose_split_kernel<<<dim3(32, 32, ZBH), dim3(32, 8)>>>(
        Of, Ph, Pl, DV_, H_ * N_,
        (long long)H_ * MB, MB,
        (long long)H_ * MB, (long long)N_,
        H_);

    // ---- 8. out[b][d,v] = sum_e wor[d,e] * P[b][v,e] : M=N=1024 K=16384
    gemm_bf16x3_wide<<<dim3(4, 8, B_), 512, SMEM_W>>>(
        worh, worl, Ph, Pl, out, nullptr, nullptr,
        H_ * N_, H_ * N_, H_ * N_, DV_,
        0, 0,
        (long long)DV_ * H_ * N_, 0,
        (long long)DM_ * DV_, 0,
        1, 1.0f, 0);
}